// round 9
// baseline (speedup 1.0000x reference)
#include <cuda_runtime.h>
#include <math.h>
#include <stdint.h>

#define S 4096
#define E 768
#define Hh 12
#define D 64
#define Wb 256
#define TT 513          // band width 2W+1
#define TQ 32           // qk: query rows per CTA
#define TQP 64          // pv: query rows per CTA
#define NKB 9           // 64-wide key blocks
#define BAND (NKB*64)   // 576 keys covered per 32-row tile
#define NEGV -1000000000.0f
#define SCALE 0.125f    // 1/sqrt(64)

// ---------------- scratch (static __device__, no allocations) ----------------
__device__ float g_q [S*E];
__device__ float g_k [S*E];
__device__ float g_v [S*E];
__device__ float g_cq[S*E];
__device__ float g_ck[S*E];
__device__ float g_lam[S*Hh];

__device__ __forceinline__ uint32_t f2tf32(float f) {
    uint32_t u;
    asm("cvt.rna.tf32.f32 %0, %1;" : "=r"(u) : "f"(f));
    return u;
}

#define MMA_TF32(acc, a0,a1,a2,a3, b0,b1)                                    \
    asm("mma.sync.aligned.m16n8k8.row.col.f32.tf32.tf32.f32 "                \
        "{%0,%1,%2,%3}, {%4,%5,%6,%7}, {%8,%9}, {%0,%1,%2,%3};"              \
        : "+f"(acc[0]), "+f"(acc[1]), "+f"(acc[2]), "+f"(acc[3])             \
        : "r"(a0), "r"(a1), "r"(a2), "r"(a3), "r"(b0), "r"(b1))

// ---------------- projection GEMM (tf32 mma.sync): C = (A @ W + b) * scale ----------------
#define GBM 128
#define GBN 64
#define GBK 32
#define ASTR 136
#define BSTR 72

__global__ __launch_bounds__(256) void gemm5_tc(
    const float* __restrict__ hs, const float* __restrict__ ce,
    const float* __restrict__ Wq,  const float* __restrict__ bq,
    const float* __restrict__ Wk,  const float* __restrict__ bk,
    const float* __restrict__ Wv,  const float* __restrict__ bv,
    const float* __restrict__ Wcq, const float* __restrict__ bcq,
    const float* __restrict__ Wck, const float* __restrict__ bck)
{
    const int which = blockIdx.z;
    const float* A;
    const float* Wt;
    const float* bias;
    float scale = 1.0f;
    float* C;
    switch (which) {
        case 0: A = hs; Wt = Wq;  bias = bq;  C = g_q;  break;
        case 1: A = hs; Wt = Wk;  bias = bk;  C = g_k;  break;
        case 2: A = hs; Wt = Wv;  bias = bv;  C = g_v;  break;
        case 3: A = ce; Wt = Wcq; bias = bcq; C = g_cq; scale = SCALE; break;
        default:A = ce; Wt = Wck; bias = bck; C = g_ck; break;
    }

    __shared__ uint32_t sA[GBK][ASTR];
    __shared__ uint32_t sB[GBK][BSTR];

    const int tid  = threadIdx.x;
    const int warp = tid >> 5;
    const int lane = tid & 31;
    const int wm   = warp & 3;
    const int wn   = warp >> 2;
    const int g    = lane >> 2;
    const int t4   = lane & 3;
    const int m0   = blockIdx.y * GBM;
    const int n0   = blockIdx.x * GBN;

    const int am = tid & 127;
    const int ak = (tid >> 7) * 16;
    const int bk2 = tid >> 3;
    const int bn2 = (tid & 7) * 8;

    const float* Abase = A  + (size_t)(m0 + am) * E + ak;
    const float* Bbase = Wt + (size_t)bk2 * E + n0 + bn2;

    float acc[2][4][4];
    #pragma unroll
    for (int mt = 0; mt < 2; mt++)
        #pragma unroll
        for (int nt = 0; nt < 4; nt++)
            #pragma unroll
            for (int x = 0; x < 4; x++) acc[mt][nt][x] = 0.f;

    for (int k0 = 0; k0 < E; k0 += GBK) {
        #pragma unroll
        for (int i = 0; i < 4; i++) {
            float4 v = *(const float4*)(Abase + k0 + i * 4);
            sA[ak + i*4 + 0][am] = f2tf32(v.x);
            sA[ak + i*4 + 1][am] = f2tf32(v.y);
            sA[ak + i*4 + 2][am] = f2tf32(v.z);
            sA[ak + i*4 + 3][am] = f2tf32(v.w);
        }
        #pragma unroll
        for (int i = 0; i < 2; i++) {
            float4 v = *(const float4*)(Bbase + (size_t)k0 * E + i * 4);
            uint4 u;
            u.x = f2tf32(v.x); u.y = f2tf32(v.y);
            u.z = f2tf32(v.z); u.w = f2tf32(v.w);
            *(uint4*)&sB[bk2][bn2 + i * 4] = u;
        }
        __syncthreads();

        #pragma unroll
        for (int ks = 0; ks < 4; ks++) {
            const int kk = ks * 8;
            uint32_t af[2][4];
            #pragma unroll
            for (int mt = 0; mt < 2; mt++) {
                int mb = wm * 32 + mt * 16 + g;
                af[mt][0] = sA[kk + t4    ][mb];
                af[mt][1] = sA[kk + t4    ][mb + 8];
                af[mt][2] = sA[kk + t4 + 4][mb];
                af[mt][3] = sA[kk + t4 + 4][mb + 8];
            }
            uint32_t bf[4][2];
            #pragma unroll
            for (int nt = 0; nt < 4; nt++) {
                int nb = wn * 32 + nt * 8 + g;
                bf[nt][0] = sB[kk + t4    ][nb];
                bf[nt][1] = sB[kk + t4 + 4][nb];
            }
            #pragma unroll
            for (int mt = 0; mt < 2; mt++)
                #pragma unroll
                for (int nt = 0; nt < 4; nt++)
                    MMA_TF32(acc[mt][nt],
                             af[mt][0], af[mt][1], af[mt][2], af[mt][3],
                             bf[nt][0], bf[nt][1]);
        }
        __syncthreads();
    }

    #pragma unroll
    for (int nt = 0; nt < 4; nt++) {
        int col = n0 + wn * 32 + nt * 8 + 2 * t4;
        float b0v = bias[col], b1v = bias[col + 1];
        #pragma unroll
        for (int mt = 0; mt < 2; mt++) {
            int row = m0 + wm * 32 + mt * 16 + g;
            float2 o;
            o.x = (acc[mt][nt][0] + b0v) * scale;
            o.y = (acc[mt][nt][1] + b1v) * scale;
            *(float2*)&C[(size_t)row * E + col] = o;
            o.x = (acc[mt][nt][2] + b0v) * scale;
            o.y = (acc[mt][nt][3] + b1v) * scale;
            *(float2*)&C[(size_t)(row + 8) * E + col] = o;
        }
    }
}

// ---------------- lam ----------------
__global__ __launch_bounds__(256) void lam_kernel(
    const float* __restrict__ Wlqc, const float* __restrict__ blqc,
    const float* __restrict__ Wlqq, const float* __restrict__ blqq,
    const float* __restrict__ Wlkc, const float* __restrict__ blkc,
    const float* __restrict__ Wlkk, const float* __restrict__ blkk)
{
    int gw   = (blockIdx.x * blockDim.x + threadIdx.x) >> 5;
    int lane = threadIdx.x & 31;
    if (gw >= S * Hh) return;
    int s = gw / Hh, h = gw % Hh;
    size_t base = (size_t)s * E + h * D;

    float a = g_cq[base + lane] * Wlqc[lane] + g_cq[base + lane + 32] * Wlqc[lane + 32]
            + g_q [base + lane] * Wlqq[lane] + g_q [base + lane + 32] * Wlqq[lane + 32];
    float b = g_ck[base + lane] * Wlkc[lane] + g_ck[base + lane + 32] * Wlkc[lane + 32]
            + g_k [base + lane] * Wlkk[lane] + g_k [base + lane + 32] * Wlkk[lane + 32];
    #pragma unroll
    for (int o = 16; o; o >>= 1) {
        a += __shfl_xor_sync(0xffffffffu, a, o);
        b += __shfl_xor_sync(0xffffffffu, b, o);
    }
    if (lane == 0) {
        float lq = 1.f / (1.f + __expf(-(a + blqc[0] + blqq[0])));
        float lk = 1.f / (1.f + __expf(-(b + blkc[0] + blkk[0])));
        g_lam[gw] = 1.f - lq - lk;
    }
}

// ---------------- band QK with tf32 MMA, whole-band smem preload ----------------
// dynsmem layout (uint32 words):
//   sK  [576][68]  @ 0       : K band, natural [c][d] tf32; B-frag bank = (4g+t4)%32, conflict-free
//   sQ  [64][40]   @ 39168   : Q^T [d][r] tf32; A-frag bank = (8t4+g)%32, conflict-free
//   sFm [576]      @ 41728   : additive key mask (float bits)
//   sSum[4][32]    @ 42304   : per-nw row sums (attn only)
#define SK_OFF  0
#define SKSTR   68
#define SQ_OFF  39168
#define QSTR    40
#define SFM_OFF 41728
#define SSUM_OFF 42304
#define QK_SMEM_WORDS 42432
#define QK_SMEM_BYTES (QK_SMEM_WORDS * 4)

// cooperative fill of sK (src row-major [j][d]) + sFm; cvt to tf32
__device__ __forceinline__ void fill_band(
    uint32_t* sm, const float* __restrict__ src, const int* __restrict__ amask,
    int q0, int h, int tid)
{
    uint32_t* sK = sm + SK_OFF;
    float* sFm = (float*)(sm + SFM_OFF);
    const int cr  = tid >> 2;          // 0..63 within 64-chunk
    const int d0l = (tid & 3) << 4;    // 0,16,32,48
    #pragma unroll
    for (int c0 = 0; c0 < BAND; c0 += 64) {
        int c = c0 + cr;
        int j = q0 - Wb + c;
        bool ok = (j >= 0) && (j < S);
        const float4* sp = (const float4*)(src + (size_t)(ok ? j : 0) * E + h * D + d0l);
        #pragma unroll
        for (int u4 = 0; u4 < 4; u4++) {
            float4 v = ok ? sp[u4] : make_float4(0.f,0.f,0.f,0.f);
            uint4 u;
            u.x = f2tf32(v.x); u.y = f2tf32(v.y);
            u.z = f2tf32(v.z); u.w = f2tf32(v.w);
            *(uint4*)&sK[c * SKSTR + d0l + u4 * 4] = u;
        }
    }
    for (int c = tid; c < BAND; c += 256) {
        int j = q0 - Wb + c;
        sFm[c] = (j >= 0 && j < S && amask[j] != 0) ? -10000.f : 0.f;
    }
}

// quasi: npout[t] = lam * sigmoid(cq.cq + mask), streaming
__global__ __launch_bounds__(256) void quasi_tc(
    const int* __restrict__ amask, float* __restrict__ npout)
{
    extern __shared__ uint32_t sm[];
    uint32_t* sK = sm + SK_OFF;
    uint32_t* sQ = sm + SQ_OFF;
    float* sFm = (float*)(sm + SFM_OFF);

    const int h   = blockIdx.y;
    const int q0  = blockIdx.x * TQ;
    const int tid = threadIdx.x;
    const int warp = tid >> 5, lane = tid & 31;
    const int mw = warp >> 2, nw = warp & 3;
    const int g = lane >> 2, t4 = lane & 3;

    // Q^T fill (cq, already scaled)
    {
        int r = tid >> 3, d0 = (tid & 7) << 3;
        const float4* qp = (const float4*)(g_cq + (size_t)(q0 + r) * E + h * D + d0);
        float4 q1 = qp[0], q2 = qp[1];
        sQ[(d0+0)*TQ + r] = f2tf32(q1.x); sQ[(d0+1)*TQ + r] = f2tf32(q1.y);
        sQ[(d0+2)*TQ + r] = f2tf32(q1.z); sQ[(d0+3)*TQ + r] = f2tf32(q1.w);
        sQ[(d0+4)*TQ + r] = f2tf32(q2.x); sQ[(d0+5)*TQ + r] = f2tf32(q2.y);
        sQ[(d0+6)*TQ + r] = f2tf32(q2.z); sQ[(d0+7)*TQ + r] = f2tf32(q2.w);
    }
    fill_band(sm, g_cq, amask, q0, h, tid);
    __syncthreads();

    const int r0 = mw * 16 + g, r1 = r0 + 8;
    const float lam0 = g_lam[(q0 + r0) * Hh + h];
    const float lam1 = g_lam[(q0 + r1) * Hh + h];
    float* np0 = npout + ((size_t)(q0 + r0) * Hh + h) * TT;
    float* np1 = npout + ((size_t)(q0 + r1) * Hh + h) * TT;
    const int mb = mw * 16 + g;

    #pragma unroll
    for (int b = 0; b < NKB; b++) {
        float acc[2][4] = {{0.f,0.f,0.f,0.f},{0.f,0.f,0.f,0.f}};
        #pragma unroll
        for (int ks = 0; ks < 8; ks++) {
            const int kk = ks * 8;
            uint32_t a0 = sQ[(kk+t4  )*TQ + mb], a1 = sQ[(kk+t4  )*TQ + mb+8];
            uint32_t a2 = sQ[(kk+t4+4)*TQ + mb], a3 = sQ[(kk+t4+4)*TQ + mb+8];
            #pragma unroll
            for (int nt = 0; nt < 2; nt++) {
                int cb = b * 64 + nw * 16 + nt * 8 + g;
                uint32_t b0 = sK[cb * SKSTR + kk + t4];
                uint32_t b1 = sK[cb * SKSTR + kk + t4 + 4];
                MMA_TF32(acc[nt], a0, a1, a2, a3, b0, b1);
            }
        }
        #pragma unroll
        for (int nt = 0; nt < 2; nt++)
            #pragma unroll
            for (int cx = 0; cx < 2; cx++) {
                int cb = b * 64 + nw * 16 + nt * 8 + 2 * t4 + cx;
                int j = q0 - Wb + cb;
                bool okj = (j >= 0) && (j < S);
                float fm = sFm[cb];
                int t0 = cb - r0;
                if (t0 >= 0 && t0 <= 512) {
                    float v = okj ? lam0 / (1.f + __expf(-(acc[nt][cx] + fm))) : 0.f;
                    np0[t0] = v;
                }
                int t1 = cb - r1;
                if (t1 >= 0 && t1 <= 512) {
                    float v = okj ? lam1 / (1.f + __expf(-(acc[nt][2+cx] + fm))) : 0.f;
                    np1[t1] = v;
                }
            }
    }
}

// attn: softmax band (register-resident) + combine with staged quasi
__global__ __launch_bounds__(256) void attn_tc(
    const int* __restrict__ amask, float* __restrict__ npout)
{
    extern __shared__ uint32_t sm[];
    uint32_t* sK = sm + SK_OFF;
    uint32_t* sQ = sm + SQ_OFF;
    float* sFm = (float*)(sm + SFM_OFF);
    float* sSum = (float*)(sm + SSUM_OFF);   // [4][32]

    const int h   = blockIdx.y;
    const int q0  = blockIdx.x * TQ;
    const int tid = threadIdx.x;
    const int warp = tid >> 5, lane = tid & 31;
    const int mw = warp >> 2, nw = warp & 3;
    const int g = lane >> 2, t4 = lane & 3;

    // Q^T fill (q, scale here)
    {
        int r = tid >> 3, d0 = (tid & 7) << 3;
        const float4* qp = (const float4*)(g_q + (size_t)(q0 + r) * E + h * D + d0);
        float4 q1 = qp[0], q2 = qp[1];
        sQ[(d0+0)*TQ + r] = f2tf32(q1.x * SCALE); sQ[(d0+1)*TQ + r] = f2tf32(q1.y * SCALE);
        sQ[(d0+2)*TQ + r] = f2tf32(q1.z * SCALE); sQ[(d0+3)*TQ + r] = f2tf32(q1.w * SCALE);
        sQ[(d0+4)*TQ + r] = f2tf32(q2.x * SCALE); sQ[(d0+5)*TQ + r] = f2tf32(q2.y * SCALE);
        sQ[(d0+6)*TQ + r] = f2tf32(q2.z * SCALE); sQ[(d0+7)*TQ + r] = f2tf32(q2.w * SCALE);
    }
    fill_band(sm, g_k, amask, q0, h, tid);
    __syncthreads();

    const int r0 = mw * 16 + g, r1 = r0 + 8;
    const int mb = mw * 16 + g;
    float aA[2][NKB*4];

    #pragma unroll
    for (int b = 0; b < NKB; b++) {
        float acc[2][4] = {{0.f,0.f,0.f,0.f},{0.f,0.f,0.f,0.f}};
        #pragma unroll
        for (int ks = 0; ks < 8; ks++) {
            const int kk = ks * 8;
            uint32_t a0 = sQ[(kk+t4  )*TQ + mb], a1 = sQ[(kk+t4  )*TQ + mb+8];
            uint32_t a2 = sQ[(kk+t4+4)*TQ + mb], a3 = sQ[(kk+t4+4)*TQ + mb+8];
            #pragma unroll
            for (int nt = 0; nt < 2; nt++) {
                int cb = b * 64 + nw * 16 + nt * 8 + g;
                uint32_t b0 = sK[cb * SKSTR + kk + t4];
                uint32_t b1 = sK[cb * SKSTR + kk + t4 + 4];
                MMA_TF32(acc[nt], a0, a1, a2, a3, b0, b1);
            }
        }
        #pragma unroll
        for (int nt = 0; nt < 2; nt++)
            #pragma unroll
            for (int cx = 0; cx < 2; cx++) {
                int cb = b * 64 + nw * 16 + nt * 8 + 2 * t4 + cx;
                int j = q0 - Wb + cb;
                float fm = sFm[cb];
                int t0 = cb - r0;
                bool v0 = (t0 >= 0) && (t0 <= 512) && (j >= 0) && (j < S);
                aA[0][b*4 + nt*2 + cx] = v0 ? (acc[nt][cx] + fm) : NEGV;
                int t1 = cb - r1;
                bool v1 = (t1 >= 0) && (t1 <= 512) && (j >= 0) && (j < S);
                aA[1][b*4 + nt*2 + cx] = v1 ? (acc[nt][2+cx] + fm) : NEGV;
            }
    }

    // softmax (no max-subtract: scores O(1) or <= -1e4 -> exp underflows to 0)
    float sum0 = 0.f, sum1 = 0.f;
    #pragma unroll
    for (int x = 0; x < NKB*4; x++) {
        float e0 = __expf(aA[0][x]); aA[0][x] = e0; sum0 += e0;
        float e1 = __expf(aA[1][x]); aA[1][x] = e1; sum1 += e1;
    }
    sum0 += __shfl_xor_sync(0xffffffffu, sum0, 1);
    sum0 += __shfl_xor_sync(0xffffffffu, sum0, 2);
    sum1 += __shfl_xor_sync(0xffffffffu, sum1, 1);
    sum1 += __shfl_xor_sync(0xffffffffu, sum1, 2);
    if (t4 == 0) { sSum[nw * 32 + r0] = sum0; sSum[nw * 32 + r1] = sum1; }
    __syncthreads();
    float inv0 = 1.f / (sSum[0*32+r0] + sSum[1*32+r0] + sSum[2*32+r0] + sSum[3*32+r0]);
    float inv1 = 1.f / (sSum[0*32+r1] + sSum[1*32+r1] + sSum[2*32+r1] + sSum[3*32+r1]);

    const int ig0 = q0 + r0, ig1 = q0 + r1;
    const bool qm0 = (amask[ig0] != 0), qm1 = (amask[ig1] != 0);
    float* np0 = npout + ((size_t)ig0 * Hh + h) * TT;
    float* np1 = npout + ((size_t)ig1 * Hh + h) * TT;

    #pragma unroll
    for (int b = 0; b < NKB; b++)
        #pragma unroll
        for (int k = 0; k < 4; k++) {
            int c = nw * 16 + (k >> 1) * 8 + 2 * t4 + (k & 1);
            int t0 = b * 64 + c - r0;
            if (t0 >= 0 && t0 <= 512) {
                float v = aA[0][b*4+k] * inv0 + np0[t0];
                np0[t0] = qm0 ? 0.f : v;
            }
            int t1 = b * 64 + c - r1;
            if (t1 >= 0 && t1 <= 512) {
                float v = aA[1][b*4+k] * inv1 + np1[t1];
                np1[t1] = qm1 ? 0.f : v;
            }
        }
}

// ---------------- PV: out = band_pv(new_probs, v) ----------------
#define PSTR 68
#define VSTR 68

__global__ __launch_bounds__(256) void pv_kernel(
    float* __restrict__ outp, const float* __restrict__ npout)
{
    __shared__ float sP[TQP * PSTR];   // [64][68]
    __shared__ float sV[64 * VSTR];    // [64][68]

    const int h   = blockIdx.y;
    const int q0  = blockIdx.x * TQP;
    const int tid = threadIdx.x;
    const int rg  = tid >> 4;          // rows 4rg..4rg+3
    const int dg  = tid & 15;          // d = 4dg..4dg+3

    float acc[4][4];
    #pragma unroll
    for (int i = 0; i < 4; i++)
        #pragma unroll
        for (int j = 0; j < 4; j++) acc[i][j] = 0.f;

    for (int b = 0; b < NKB; b++) {
        int kb0 = q0 - Wb + b * 64;
        __syncthreads();
        {
            int lr  = tid >> 2;
            int c0l = (tid & 3) << 4;
            const float* nprow = npout + ((size_t)(q0 + lr) * Hh + h) * TT;
            #pragma unroll
            for (int x4 = 0; x4 < 4; x4++) {
                int t0 = b * 64 + c0l + x4 * 4 - lr;
                float4 pv4;
                pv4.x = (t0+0 >= 0 && t0+0 <= 512) ? nprow[t0+0] : 0.f;
                pv4.y = (t0+1 >= 0 && t0+1 <= 512) ? nprow[t0+1] : 0.f;
                pv4.z = (t0+2 >= 0 && t0+2 <= 512) ? nprow[t0+2] : 0.f;
                pv4.w = (t0+3 >= 0 && t0+3 <= 512) ? nprow[t0+3] : 0.f;
                *(float4*)&sP[lr * PSTR + c0l + x4 * 4] = pv4;
            }
        }
        {
            int c   = tid >> 2;
            int d0l = (tid & 3) << 4;
            int j = kb0 + c;
            bool ok = (j >= 0) && (j < S);
            const float4* vp = (const float4*)(g_v + (size_t)(ok ? j : 0) * E + h * D + d0l);
            #pragma unroll
            for (int u4 = 0; u4 < 4; u4++) {
                float4 x = ok ? vp[u4] : make_float4(0.f,0.f,0.f,0.f);
                *(float4*)&sV[c * VSTR + d0l + u4 * 4] = x;
            }
        }
        __syncthreads();

        #pragma unroll 4
        for (int c = 0; c < 64; c++) {
            float4 vv = *(const float4*)&sV[c * VSTR + 4 * dg];
            float p0 = sP[(4*rg+0) * PSTR + c];
            float p1 = sP[(4*rg+1) * PSTR + c];
            float p2 = sP[(4*rg+2) * PSTR + c];
            float p3 = sP[(4*rg+3) * PSTR + c];
            acc[0][0] += p0*vv.x; acc[0][1] += p0*vv.y; acc[0][2] += p0*vv.z; acc[0][3] += p0*vv.w;
            acc[1][0] += p1*vv.x; acc[1][1] += p1*vv.y; acc[1][2] += p1*vv.z; acc[1][3] += p1*vv.w;
            acc[2][0] += p2*vv.x; acc[2][1] += p2*vv.y; acc[2][2] += p2*vv.z; acc[2][3] += p2*vv.w;
            acc[3][0] += p3*vv.x; acc[3][1] += p3*vv.y; acc[3][2] += p3*vv.z; acc[3][3] += p3*vv.w;
        }
    }

    #pragma unroll
    for (int i = 0; i < 4; i++) {
        float4 o;
        o.x = acc[i][0]; o.y = acc[i][1]; o.z = acc[i][2]; o.w = acc[i][3];
        *(float4*)(outp + (size_t)(q0 + 4*rg + i) * E + h * D + 4 * dg) = o;
    }
}

// ---------------- launch ----------------
extern "C" void kernel_launch(void* const* d_in, const int* in_sizes, int n_in,
                              void* d_out, int out_size)
{
    (void)in_sizes; (void)n_in; (void)out_size;

    const float* hs    = (const float*)d_in[0];
    const float* ce    = (const float*)d_in[1];
    const int*   amask = (const int*)  d_in[2];
    // d_in[3] is is_index_masked == (attention_mask != 0); derived from amask.
    const float* Wq   = (const float*)d_in[4];
    const float* bq   = (const float*)d_in[5];
    const float* Wk   = (const float*)d_in[6];
    const float* bk   = (const float*)d_in[7];
    const float* Wv   = (const float*)d_in[8];
    const float* bv   = (const float*)d_in[9];
    const float* Wcq  = (const float*)d_in[10];
    const float* bcq  = (const float*)d_in[11];
    const float* Wck  = (const float*)d_in[12];
    const float* bck  = (const float*)d_in[13];
    const float* Wlqc = (const float*)d_in[14];
    const float* blqc = (const float*)d_in[15];
    const float* Wlqq = (const float*)d_in[16];
    const float* blqq = (const float*)d_in[17];
    const float* Wlkc = (const float*)d_in[18];
    const float* blkc = (const float*)d_in[19];
    const float* Wlkk = (const float*)d_in[20];
    const float* blkk = (const float*)d_in[21];

    float* outp  = (float*)d_out;
    float* npout = outp + (size_t)S * E;   // tuple output: [out | new_probs]

    cudaFuncSetAttribute(quasi_tc, cudaFuncAttributeMaxDynamicSharedMemorySize, QK_SMEM_BYTES);
    cudaFuncSetAttribute(attn_tc,  cudaFuncAttributeMaxDynamicSharedMemorySize, QK_SMEM_BYTES);

    dim3 gg(E / GBN, S / GBM, 5);
    gemm5_tc<<<gg, 256>>>(hs, ce, Wq, bq, Wk, bk, Wv, bv, Wcq, bcq, Wck, bck);

    lam_kernel<<<(S * Hh) / 8, 256>>>(Wlqc, blqc, Wlqq, blqq, Wlkc, blkc, Wlkk, blkk);

    quasi_tc<<<dim3(S / TQ, Hh), 256, QK_SMEM_BYTES>>>(amask, npout);

    attn_tc<<<dim3(S / TQ, Hh), 256, QK_SMEM_BYTES>>>(amask, npout);

    pv_kernel<<<dim3(S / TQP, Hh), 256>>>(outp, npout);
}

// round 11
// speedup vs baseline: 1.1322x; 1.1322x over previous
#include <cuda_runtime.h>
#include <math.h>
#include <stdint.h>

#define S 4096
#define E 768
#define Hh 12
#define D 64
#define Wb 256
#define TT 513          // band width 2W+1
#define TQ 32           // qk: query rows per CTA
#define TQP 64          // pv: query rows per CTA
#define NKB 9           // 64-wide key blocks
#define NEGV -1000000000.0f
#define SCALE 0.125f    // 1/sqrt(64)

// ---------------- scratch (static __device__, no allocations) ----------------
__device__ float g_q [S*E];
__device__ float g_k [S*E];
__device__ float g_v [S*E];
__device__ float g_cq[S*E];
__device__ float g_ck[S*E];
__device__ float g_lam[S*Hh];

__device__ __forceinline__ uint32_t f2tf32(float f) {
    uint32_t u;
    asm("cvt.rna.tf32.f32 %0, %1;" : "=r"(u) : "f"(f));
    return u;
}

#define MMA_TF32(acc, a0,a1,a2,a3, b0,b1)                                    \
    asm("mma.sync.aligned.m16n8k8.row.col.f32.tf32.tf32.f32 "                \
        "{%0,%1,%2,%3}, {%4,%5,%6,%7}, {%8,%9}, {%0,%1,%2,%3};"              \
        : "+f"(acc[0]), "+f"(acc[1]), "+f"(acc[2]), "+f"(acc[3])             \
        : "r"(a0), "r"(a1), "r"(a2), "r"(a3), "r"(b0), "r"(b1))

// ---------------- projection GEMM (tf32 mma.sync, double-buffered, dyn smem) ----------------
#define GBM 128
#define GBN 64
#define GBK 32
#define ASTR 136
#define BSTR 72
// dynamic smem words: 2 A buffers + 2 B buffers
#define GA_WORDS (GBK * ASTR)
#define GB_WORDS (GBK * BSTR)
#define GEMM_SMEM_WORDS (2 * GA_WORDS + 2 * GB_WORDS)
#define GEMM_SMEM_BYTES (GEMM_SMEM_WORDS * 4)   // 53248

__global__ __launch_bounds__(256) void gemm5_tc(
    const float* __restrict__ hs, const float* __restrict__ ce,
    const float* __restrict__ Wq,  const float* __restrict__ bq,
    const float* __restrict__ Wk,  const float* __restrict__ bk,
    const float* __restrict__ Wv,  const float* __restrict__ bv,
    const float* __restrict__ Wcq, const float* __restrict__ bcq,
    const float* __restrict__ Wck, const float* __restrict__ bck)
{
    const int which = blockIdx.z;
    const float* A;
    const float* Wt;
    const float* bias;
    float scale = 1.0f;
    float* C;
    switch (which) {
        case 0: A = hs; Wt = Wq;  bias = bq;  C = g_q;  break;
        case 1: A = hs; Wt = Wk;  bias = bk;  C = g_k;  break;
        case 2: A = hs; Wt = Wv;  bias = bv;  C = g_v;  break;
        case 3: A = ce; Wt = Wcq; bias = bcq; C = g_cq; scale = SCALE; break;
        default:A = ce; Wt = Wck; bias = bck; C = g_ck; break;
    }

    extern __shared__ uint32_t dsm[];
    uint32_t* pA[2] = { dsm,                dsm + GA_WORDS };
    uint32_t* pB[2] = { dsm + 2*GA_WORDS,   dsm + 2*GA_WORDS + GB_WORDS };

    const int tid  = threadIdx.x;
    const int warp = tid >> 5;
    const int lane = tid & 31;
    const int wm   = warp & 3;
    const int wn   = warp >> 2;
    const int g    = lane >> 2;
    const int t4   = lane & 3;
    const int m0   = blockIdx.y * GBM;
    const int n0   = blockIdx.x * GBN;

    const int am = tid & 127;
    const int ak = (tid >> 7) * 16;
    const int bk2 = tid >> 3;
    const int bn2 = (tid & 7) * 8;

    const float* Abase = A  + (size_t)(m0 + am) * E + ak;
    const float* Bbase = Wt + (size_t)bk2 * E + n0 + bn2;

    float acc[2][4][4];
    #pragma unroll
    for (int mt = 0; mt < 2; mt++)
        #pragma unroll
        for (int nt = 0; nt < 4; nt++)
            #pragma unroll
            for (int x = 0; x < 4; x++) acc[mt][nt][x] = 0.f;

    // preload tile 0 into buffer 0
    {
        uint32_t* sA0 = pA[0];
        uint32_t* sB0 = pB[0];
        float4 a0v = *(const float4*)(Abase);
        float4 a1v = *(const float4*)(Abase + 4);
        float4 a2v = *(const float4*)(Abase + 8);
        float4 a3v = *(const float4*)(Abase + 12);
        sA0[(ak + 0)*ASTR + am] = f2tf32(a0v.x); sA0[(ak + 1)*ASTR + am] = f2tf32(a0v.y);
        sA0[(ak + 2)*ASTR + am] = f2tf32(a0v.z); sA0[(ak + 3)*ASTR + am] = f2tf32(a0v.w);
        sA0[(ak + 4)*ASTR + am] = f2tf32(a1v.x); sA0[(ak + 5)*ASTR + am] = f2tf32(a1v.y);
        sA0[(ak + 6)*ASTR + am] = f2tf32(a1v.z); sA0[(ak + 7)*ASTR + am] = f2tf32(a1v.w);
        sA0[(ak + 8)*ASTR + am] = f2tf32(a2v.x); sA0[(ak + 9)*ASTR + am] = f2tf32(a2v.y);
        sA0[(ak +10)*ASTR + am] = f2tf32(a2v.z); sA0[(ak +11)*ASTR + am] = f2tf32(a2v.w);
        sA0[(ak +12)*ASTR + am] = f2tf32(a3v.x); sA0[(ak +13)*ASTR + am] = f2tf32(a3v.y);
        sA0[(ak +14)*ASTR + am] = f2tf32(a3v.z); sA0[(ak +15)*ASTR + am] = f2tf32(a3v.w);
        float4 b0v = *(const float4*)(Bbase);
        float4 b1v = *(const float4*)(Bbase + 4);
        uint4 u0, u1;
        u0.x = f2tf32(b0v.x); u0.y = f2tf32(b0v.y); u0.z = f2tf32(b0v.z); u0.w = f2tf32(b0v.w);
        u1.x = f2tf32(b1v.x); u1.y = f2tf32(b1v.y); u1.z = f2tf32(b1v.z); u1.w = f2tf32(b1v.w);
        *(uint4*)&sB0[bk2*BSTR + bn2]     = u0;
        *(uint4*)&sB0[bk2*BSTR + bn2 + 4] = u1;
    }
    __syncthreads();

    int cur = 0;
    for (int k0 = 0; k0 < E; k0 += GBK) {
        const bool more = (k0 + GBK < E);
        float4 pa0, pa1, pa2, pa3, pb0, pb1;
        if (more) {
            pa0 = *(const float4*)(Abase + k0 + GBK);
            pa1 = *(const float4*)(Abase + k0 + GBK + 4);
            pa2 = *(const float4*)(Abase + k0 + GBK + 8);
            pa3 = *(const float4*)(Abase + k0 + GBK + 12);
            pb0 = *(const float4*)(Bbase + (size_t)(k0 + GBK) * E);
            pb1 = *(const float4*)(Bbase + (size_t)(k0 + GBK) * E + 4);
        }

        const uint32_t* sAc = pA[cur];
        const uint32_t* sBc = pB[cur];
        #pragma unroll
        for (int ks = 0; ks < 4; ks++) {
            const int kk = ks * 8;
            uint32_t af[2][4];
            #pragma unroll
            for (int mt = 0; mt < 2; mt++) {
                int mb = wm * 32 + mt * 16 + g;
                af[mt][0] = sAc[(kk + t4    )*ASTR + mb];
                af[mt][1] = sAc[(kk + t4    )*ASTR + mb + 8];
                af[mt][2] = sAc[(kk + t4 + 4)*ASTR + mb];
                af[mt][3] = sAc[(kk + t4 + 4)*ASTR + mb + 8];
            }
            uint32_t bf[4][2];
            #pragma unroll
            for (int nt = 0; nt < 4; nt++) {
                int nb = wn * 32 + nt * 8 + g;
                bf[nt][0] = sBc[(kk + t4    )*BSTR + nb];
                bf[nt][1] = sBc[(kk + t4 + 4)*BSTR + nb];
            }
            #pragma unroll
            for (int mt = 0; mt < 2; mt++)
                #pragma unroll
                for (int nt = 0; nt < 4; nt++)
                    MMA_TF32(acc[mt][nt],
                             af[mt][0], af[mt][1], af[mt][2], af[mt][3],
                             bf[nt][0], bf[nt][1]);
        }

        if (more) {
            int nxt = cur ^ 1;
            uint32_t* sAn = pA[nxt];
            uint32_t* sBn = pB[nxt];
            sAn[(ak + 0)*ASTR + am] = f2tf32(pa0.x); sAn[(ak + 1)*ASTR + am] = f2tf32(pa0.y);
            sAn[(ak + 2)*ASTR + am] = f2tf32(pa0.z); sAn[(ak + 3)*ASTR + am] = f2tf32(pa0.w);
            sAn[(ak + 4)*ASTR + am] = f2tf32(pa1.x); sAn[(ak + 5)*ASTR + am] = f2tf32(pa1.y);
            sAn[(ak + 6)*ASTR + am] = f2tf32(pa1.z); sAn[(ak + 7)*ASTR + am] = f2tf32(pa1.w);
            sAn[(ak + 8)*ASTR + am] = f2tf32(pa2.x); sAn[(ak + 9)*ASTR + am] = f2tf32(pa2.y);
            sAn[(ak +10)*ASTR + am] = f2tf32(pa2.z); sAn[(ak +11)*ASTR + am] = f2tf32(pa2.w);
            sAn[(ak +12)*ASTR + am] = f2tf32(pa3.x); sAn[(ak +13)*ASTR + am] = f2tf32(pa3.y);
            sAn[(ak +14)*ASTR + am] = f2tf32(pa3.z); sAn[(ak +15)*ASTR + am] = f2tf32(pa3.w);
            uint4 u0, u1;
            u0.x = f2tf32(pb0.x); u0.y = f2tf32(pb0.y); u0.z = f2tf32(pb0.z); u0.w = f2tf32(pb0.w);
            u1.x = f2tf32(pb1.x); u1.y = f2tf32(pb1.y); u1.z = f2tf32(pb1.z); u1.w = f2tf32(pb1.w);
            *(uint4*)&sBn[bk2*BSTR + bn2]     = u0;
            *(uint4*)&sBn[bk2*BSTR + bn2 + 4] = u1;
            __syncthreads();
            cur = nxt;
        }
    }

    #pragma unroll
    for (int nt = 0; nt < 4; nt++) {
        int col = n0 + wn * 32 + nt * 8 + 2 * t4;
        float b0v = bias[col], b1v = bias[col + 1];
        #pragma unroll
        for (int mt = 0; mt < 2; mt++) {
            int row = m0 + wm * 32 + mt * 16 + g;
            float2 o;
            o.x = (acc[mt][nt][0] + b0v) * scale;
            o.y = (acc[mt][nt][1] + b1v) * scale;
            *(float2*)&C[(size_t)row * E + col] = o;
            o.x = (acc[mt][nt][2] + b0v) * scale;
            o.y = (acc[mt][nt][3] + b1v) * scale;
            *(float2*)&C[(size_t)(row + 8) * E + col] = o;
        }
    }
}

// ---------------- lam ----------------
__global__ __launch_bounds__(256) void lam_kernel(
    const float* __restrict__ Wlqc, const float* __restrict__ blqc,
    const float* __restrict__ Wlqq, const float* __restrict__ blqq,
    const float* __restrict__ Wlkc, const float* __restrict__ blkc,
    const float* __restrict__ Wlkk, const float* __restrict__ blkk)
{
    int gw   = (blockIdx.x * blockDim.x + threadIdx.x) >> 5;
    int lane = threadIdx.x & 31;
    if (gw >= S * Hh) return;
    int s = gw / Hh, h = gw % Hh;
    size_t base = (size_t)s * E + h * D;

    float a = g_cq[base + lane] * Wlqc[lane] + g_cq[base + lane + 32] * Wlqc[lane + 32]
            + g_q [base + lane] * Wlqq[lane] + g_q [base + lane + 32] * Wlqq[lane + 32];
    float b = g_ck[base + lane] * Wlkc[lane] + g_ck[base + lane + 32] * Wlkc[lane + 32]
            + g_k [base + lane] * Wlkk[lane] + g_k [base + lane + 32] * Wlkk[lane + 32];
    #pragma unroll
    for (int o = 16; o; o >>= 1) {
        a += __shfl_xor_sync(0xffffffffu, a, o);
        b += __shfl_xor_sync(0xffffffffu, b, o);
    }
    if (lane == 0) {
        float lq = 1.f / (1.f + __expf(-(a + blqc[0] + blqq[0])));
        float lk = 1.f / (1.f + __expf(-(b + blkc[0] + blkk[0])));
        g_lam[gw] = 1.f - lq - lk;
    }
}

// ---------------- quasi kernel (SIMT, R7 winner): npout[t] = lam * sigmoid(cq.cq + mask) ----------------
#define KSTR 64

__global__ __launch_bounds__(256) void quasi_kernel(
    const int* __restrict__ amask, float* __restrict__ npout)
{
    __shared__ float sCQT[64 * TQ];    // cq^T for query rows
    __shared__ float sCKT[64 * KSTR];  // cq key-block^T
    __shared__ float sFm[64];

    const int h   = blockIdx.y;
    const int q0  = blockIdx.x * TQ;
    const int tid = threadIdx.x;
    const int rg  = tid >> 4;          // 0..15
    const int cg  = tid & 15;
    const int r0  = rg << 1;           // rows r0, r0+1
    const int c0  = cg << 2;           // cols c0..c0+3

    {
        int lr = tid >> 3;             // 0..31
        int d0 = (tid & 7) << 3;       // 8 floats each
        const float4* cqp = (const float4*)(g_cq + (size_t)(q0 + lr) * E + h * D + d0);
        float4 c1 = cqp[0], c2 = cqp[1];
        sCQT[(d0+0)*TQ + lr] = c1.x; sCQT[(d0+1)*TQ + lr] = c1.y;
        sCQT[(d0+2)*TQ + lr] = c1.z; sCQT[(d0+3)*TQ + lr] = c1.w;
        sCQT[(d0+4)*TQ + lr] = c2.x; sCQT[(d0+5)*TQ + lr] = c2.y;
        sCQT[(d0+6)*TQ + lr] = c2.z; sCQT[(d0+7)*TQ + lr] = c2.w;
    }

    const float lam0 = g_lam[(q0 + r0 + 0) * Hh + h];
    const float lam1 = g_lam[(q0 + r0 + 1) * Hh + h];
    float* nprow0 = npout + ((size_t)(q0 + r0 + 0) * Hh + h) * TT;
    float* nprow1 = npout + ((size_t)(q0 + r0 + 1) * Hh + h) * TT;

    const int lc  = tid >> 2;          // 0..63
    const int ld0 = (tid & 3) << 4;    // 0,16,32,48

    for (int b = 0; b < NKB; b++) {
        const int kb0 = q0 - Wb + b * 64;
        __syncthreads();
        {
            int j = kb0 + lc;
            bool ok = (j >= 0) && (j < S);
            const float4* cp = (const float4*)(g_cq + (size_t)(ok ? j : 0) * E + h * D + ld0);
            #pragma unroll
            for (int u4 = 0; u4 < 4; u4++) {
                float4 cv = ok ? cp[u4] : make_float4(0.f,0.f,0.f,0.f);
                int dd = ld0 + u4 * 4;
                sCKT[(dd+0)*KSTR + lc] = cv.x; sCKT[(dd+1)*KSTR + lc] = cv.y;
                sCKT[(dd+2)*KSTR + lc] = cv.z; sCKT[(dd+3)*KSTR + lc] = cv.w;
            }
            if (tid < 64) {
                int jj = kb0 + tid;
                sFm[tid] = (jj >= 0 && jj < S && amask[jj] != 0) ? -10000.f : 0.f;
            }
        }
        __syncthreads();

        float acq[2][4] = {{0.f,0.f,0.f,0.f},{0.f,0.f,0.f,0.f}};
        #pragma unroll 8
        for (int kk = 0; kk < 64; kk++) {
            float2 cqv = *(const float2*)&sCQT[kk*TQ  + r0];
            float4 ckv = *(const float4*)&sCKT[kk*KSTR + c0];
            acq[0][0] += cqv.x*ckv.x; acq[0][1] += cqv.x*ckv.y;
            acq[0][2] += cqv.x*ckv.z; acq[0][3] += cqv.x*ckv.w;
            acq[1][0] += cqv.y*ckv.x; acq[1][1] += cqv.y*ckv.y;
            acq[1][2] += cqv.y*ckv.z; acq[1][3] += cqv.y*ckv.w;
        }

        #pragma unroll
        for (int jx = 0; jx < 4; jx++) {
            int c = c0 + jx;
            int j = kb0 + c;
            bool okj = (j >= 0) && (j < S);
            float fm = sFm[c];
            {
                int t = b * 64 + c - (r0 + 0);
                if (t >= 0 && t <= 512) {
                    float v = okj ? lam0 / (1.f + __expf(-(acq[0][jx] + fm))) : 0.f;
                    nprow0[t] = v;
                }
            }
            {
                int t = b * 64 + c - (r0 + 1);
                if (t >= 0 && t <= 512) {
                    float v = okj ? lam1 / (1.f + __expf(-(acq[1][jx] + fm))) : 0.f;
                    nprow1[t] = v;
                }
            }
        }
    }
}

// ---------------- attn kernel (SIMT, R7 winner): softmax band + combine with staged quasi ----------------
__global__ __launch_bounds__(256, 2) void attn_kernel(
    const int* __restrict__ amask, float* __restrict__ npout)
{
    __shared__ float sQT[64 * TQ];     // q^T (pre-scaled)
    __shared__ float sKT[64 * KSTR];   // k^T
    __shared__ float sFm[64];

    const int h   = blockIdx.y;
    const int q0  = blockIdx.x * TQ;
    const int tid = threadIdx.x;
    const int rg  = tid >> 4;
    const int cg  = tid & 15;
    const int r0  = rg << 1;
    const int c0  = cg << 2;

    {
        int lr = tid >> 3;
        int d0 = (tid & 7) << 3;
        const float4* qp = (const float4*)(g_q + (size_t)(q0 + lr) * E + h * D + d0);
        float4 q1 = qp[0], q2 = qp[1];
        sQT[(d0+0)*TQ + lr] = q1.x * SCALE; sQT[(d0+1)*TQ + lr] = q1.y * SCALE;
        sQT[(d0+2)*TQ + lr] = q1.z * SCALE; sQT[(d0+3)*TQ + lr] = q1.w * SCALE;
        sQT[(d0+4)*TQ + lr] = q2.x * SCALE; sQT[(d0+5)*TQ + lr] = q2.y * SCALE;
        sQT[(d0+6)*TQ + lr] = q2.z * SCALE; sQT[(d0+7)*TQ + lr] = q2.w * SCALE;
    }

    float aA[2][NKB*4];   // attn band (scores, then exp)

    const int lc  = tid >> 2;
    const int ld0 = (tid & 3) << 4;

    #pragma unroll
    for (int b = 0; b < NKB; b++) {
        const int kb0 = q0 - Wb + b * 64;
        __syncthreads();
        {
            int j = kb0 + lc;
            bool ok = (j >= 0) && (j < S);
            const float4* kp = (const float4*)(g_k + (size_t)(ok ? j : 0) * E + h * D + ld0);
            #pragma unroll
            for (int u4 = 0; u4 < 4; u4++) {
                float4 kv = ok ? kp[u4] : make_float4(0.f,0.f,0.f,0.f);
                int dd = ld0 + u4 * 4;
                sKT[(dd+0)*KSTR + lc] = kv.x; sKT[(dd+1)*KSTR + lc] = kv.y;
                sKT[(dd+2)*KSTR + lc] = kv.z; sKT[(dd+3)*KSTR + lc] = kv.w;
            }
            if (tid < 64) {
                int jj = kb0 + tid;
                sFm[tid] = (jj >= 0 && jj < S && amask[jj] != 0) ? -10000.f : 0.f;
            }
        }
        __syncthreads();

        float acc[2][4] = {{0.f,0.f,0.f,0.f},{0.f,0.f,0.f,0.f}};
        #pragma unroll 8
        for (int kk = 0; kk < 64; kk++) {
            float2 qv = *(const float2*)&sQT[kk*TQ  + r0];
            float4 kv = *(const float4*)&sKT[kk*KSTR + c0];
            acc[0][0] += qv.x*kv.x; acc[0][1] += qv.x*kv.y;
            acc[0][2] += qv.x*kv.z; acc[0][3] += qv.x*kv.w;
            acc[1][0] += qv.y*kv.x; acc[1][1] += qv.y*kv.y;
            acc[1][2] += qv.y*kv.z; acc[1][3] += qv.y*kv.w;
        }

        #pragma unroll
        for (int i = 0; i < 2; i++) {
            int r = r0 + i;
            #pragma unroll
            for (int jx = 0; jx < 4; jx++) {
                int c = c0 + jx;
                int t = b * 64 + c - r;
                int j = kb0 + c;
                bool valid = (t >= 0) && (t <= 512) && (j >= 0) && (j < S);
                aA[i][b*4+jx] = valid ? (acc[i][jx] + sFm[c]) : NEGV;
            }
        }
    }

    #pragma unroll
    for (int i = 0; i < 2; i++) {
        int r  = r0 + i;
        int ig = q0 + r;
        float m = NEGV;
        #pragma unroll
        for (int x = 0; x < NKB*4; x++) m = fmaxf(m, aA[i][x]);
        #pragma unroll
        for (int o = 8; o; o >>= 1) m = fmaxf(m, __shfl_xor_sync(0xffffffffu, m, o));
        float ssum = 0.f;
        #pragma unroll
        for (int x = 0; x < NKB*4; x++) {
            float e = __expf(aA[i][x] - m);
            aA[i][x] = e;
            ssum += e;
        }
        #pragma unroll
        for (int o = 8; o; o >>= 1) ssum += __shfl_xor_sync(0xffffffffu, ssum, o);
        float inv = 1.f / ssum;
        bool  qm  = (amask[ig] != 0);
        float* nprow = npout + ((size_t)ig * Hh + h) * TT;
        #pragma unroll
        for (int b = 0; b < NKB; b++) {
            #pragma unroll
            for (int jx = 0; jx < 4; jx++) {
                int t = b * 64 + c0 + jx - r;
                if (t >= 0 && t <= 512) {
                    float np = aA[i][b*4+jx] * inv + nprow[t];
                    nprow[t] = qm ? 0.f : np;
                }
            }
        }
    }
}

// ---------------- PV with tf32 MMA: out = band_pv(new_probs, v) ----------------
// Per CTA: 64 q-rows; per 64-key block a dense 64x64x64 GEMM on smem tiles.
// sP[r][c] tf32 (A, row-major m=r,k=c): frag banks (4g+t4)%32 conflict-free.
// sV[c][d] tf32 (B, col-major k=c,n=d): frag banks (4t4+g)%32 conflict-free.
#define PSTR 68
#define VSTR 68

__global__ __launch_bounds__(256) void pv_tc(
    float* __restrict__ outp, const float* __restrict__ npout)
{
    __shared__ uint32_t sP[TQP * PSTR];   // [64][68] tf32
    __shared__ uint32_t sV[64 * VSTR];    // [64][68] tf32

    const int h   = blockIdx.y;
    const int q0  = blockIdx.x * TQP;
    const int tid = threadIdx.x;
    const int warp = tid >> 5, lane = tid & 31;
    const int mw = warp >> 1;          // 0..3 -> rows 16mw..16mw+15
    const int nw = warp & 1;           // 0..1 -> cols 32nw..32nw+31
    const int g = lane >> 2, t4 = lane & 3;

    float acc[4][4];
    #pragma unroll
    for (int nt = 0; nt < 4; nt++)
        #pragma unroll
        for (int x = 0; x < 4; x++) acc[nt][x] = 0.f;

    for (int b = 0; b < NKB; b++) {
        int kb0 = q0 - Wb + b * 64;
        __syncthreads();
        // load p tile (band gather, tf32)
        {
            int lr  = tid >> 2;            // 0..63
            int c0l = (tid & 3) << 4;      // 0,16,32,48
            const float* nprow = npout + ((size_t)(q0 + lr) * Hh + h) * TT;
            #pragma unroll
            for (int x4 = 0; x4 < 4; x4++) {
                int t0 = b * 64 + c0l + x4 * 4 - lr;
                uint4 u;
                u.x = (t0+0 >= 0 && t0+0 <= 512) ? f2tf32(nprow[t0+0]) : 0u;
                u.y = (t0+1 >= 0 && t0+1 <= 512) ? f2tf32(nprow[t0+1]) : 0u;
                u.z = (t0+2 >= 0 && t0+2 <= 512) ? f2tf32(nprow[t0+2]) : 0u;
                u.w = (t0+3 >= 0 && t0+3 <= 512) ? f2tf32(nprow[t0+3]) : 0u;
                *(uint4*)&sP[lr * PSTR + c0l + x4 * 4] = u;
            }
        }
        // load v tile [c][d] (tf32)
        {
            int c   = tid >> 2;            // 0..63
            int d0l = (tid & 3) << 4;      // 0,16,32,48
            int j = kb0 + c;
            bool ok = (j >= 0) && (j < S);
            const float4* vp = (const float4*)(g_v + (size_t)(ok ? j : 0) * E + h * D + d0l);
            #pragma unroll
            for (int u4 = 0; u4 < 4; u4++) {
                float4 x = ok ? vp[u4] : make_float4(0.f,0.f,0.f,0.f);
                uint4 u;
                u.x = f2tf32(x.x); u.y = f2tf32(x.y);
                u.z = f2tf32(x.z); u.w = f2tf32(x.w);
                *(uint4*)&sV[c * VSTR + d0l + u4 * 4] = u;
            }
        }
        __syncthreads();

        const int m0l = mw * 16;
        #pragma unroll
        for (int ks = 0; ks < 8; ks++) {
            const int kk = ks * 8;
            uint32_t a0 = sP[(m0l + g    ) * PSTR + kk + t4];
            uint32_t a1 = sP[(m0l + g + 8) * PSTR + kk + t4];
            uint32_t a2 = sP[(m0l + g    ) * PSTR + kk + t4 + 4];
            uint32_t a3 = sP[(m0l + g + 8) * PSTR + kk + t4 + 4];
            #pragma unroll
            for (int nt = 0; nt < 4; nt++) {
                int nb = nw * 32 + nt * 8 + g;
                uint32_t b0 = sV[(kk + t4    ) * VSTR + nb];
                uint32_t b1 = sV[(kk + t4 + 4) * VSTR + nb];
                MMA_TF32(acc[nt], a0, a1, a2, a3, b0, b1);
            }
        }
    }

    // epilogue
    #pragma unroll
    for (int nt = 0; nt < 4; nt++) {
        int col = nw * 32 + nt * 8 + 2 * t4;
        int row = q0 + mw * 16 + g;
        float2 o;
        o.x = acc[nt][0]; o.y = acc[nt][1];
        *(float2*)(outp + (size_t)row * E + h * D + col) = o;
        o.x = acc[nt][2]; o.y = acc[nt][3];
        *(float2*)(outp + (size_t)(row + 8) * E + h * D + col) = o;
    }
}

// ---------------- launch ----------------
extern "C" void kernel_launch(void* const* d_in, const int* in_sizes, int n_in,
                              void* d_out, int out_size)
{
    (void)in_sizes; (void)n_in; (void)out_size;

    const float* hs    = (const float*)d_in[0];
    const float* ce    = (const float*)d_in[1];
    const int*   amask = (const int*)  d_in[2];
    // d_in[3] is is_index_masked == (attention_mask != 0); derived from amask.
    const float* Wq   = (const float*)d_in[4];
    const float* bq   = (const float*)d_in[5];
    const float* Wk   = (const float*)d_in[6];
    const float* bk   = (const float*)d_in[7];
    const float* Wv   = (const float*)d_in[8];
    const float* bv   = (const float*)d_in[9];
    const float* Wcq  = (const float*)d_in[10];
    const float* bcq  = (const float*)d_in[11];
    const float* Wck  = (const float*)d_in[12];
    const float* bck  = (const float*)d_in[13];
    const float* Wlqc = (const float*)d_in[14];
    const float* blqc = (const float*)d_in[15];
    const float* Wlqq = (const float*)d_in[16];
    const float* blqq = (const float*)d_in[17];
    const float* Wlkc = (const float*)d_in[18];
    const float* blkc = (const float*)d_in[19];
    const float* Wlkk = (const float*)d_in[20];
    const float* blkk = (const float*)d_in[21];

    float* outp  = (float*)d_out;
    float* npout = outp + (size_t)S * E;   // tuple output: [out | new_probs]

    cudaFuncSetAttribute(gemm5_tc, cudaFuncAttributeMaxDynamicSharedMemorySize,
                         GEMM_SMEM_BYTES);

    dim3 gg(E / GBN, S / GBM, 5);
    gemm5_tc<<<gg, 256, GEMM_SMEM_BYTES>>>(hs, ce, Wq, bq, Wk, bk, Wv, bv, Wcq, bcq, Wck, bck);

    lam_kernel<<<(S * Hh) / 8, 256>>>(Wlqc, blqc, Wlqq, blqq, Wlkc, blkc, Wlkk, blkk);

    quasi_kernel<<<dim3(S / TQ, Hh), 256>>>(amask, npout);

    attn_kernel<<<dim3(S / TQ, Hh), 256>>>(amask, npout);

    pv_tc<<<dim3(S / TQP, Hh), 256>>>(outp, npout);
}

// round 12
// speedup vs baseline: 1.1874x; 1.0487x over previous
#include <cuda_runtime.h>
#include <math.h>
#include <stdint.h>

#define S 4096
#define E 768
#define Hh 12
#define D 64
#define Wb 256
#define TT 513          // band width 2W+1
#define TQ 32           // qk: query rows per CTA
#define TQP 64          // pv: query rows per CTA
#define NKB 9           // 64-wide key blocks
#define NEGV -1000000000.0f
#define SCALE 0.125f    // 1/sqrt(64)

// ---------------- scratch (static __device__, no allocations) ----------------
__device__ float g_q [S*E];
__device__ float g_k [S*E];
__device__ float g_v [S*E];
__device__ float g_cq[S*E];
__device__ float g_ck[S*E];
__device__ float g_lam[S*Hh];

__device__ __forceinline__ uint32_t f2tf32(float f) {
    uint32_t u;
    asm("cvt.rna.tf32.f32 %0, %1;" : "=r"(u) : "f"(f));
    return u;
}

#define MMA_TF32(acc, a0,a1,a2,a3, b0,b1)                                    \
    asm("mma.sync.aligned.m16n8k8.row.col.f32.tf32.tf32.f32 "                \
        "{%0,%1,%2,%3}, {%4,%5,%6,%7}, {%8,%9}, {%0,%1,%2,%3};"              \
        : "+f"(acc[0]), "+f"(acc[1]), "+f"(acc[2]), "+f"(acc[3])             \
        : "r"(a0), "r"(a1), "r"(a2), "r"(a3), "r"(b0), "r"(b1))

// ---------------- projection GEMM (tf32 mma.sync, single-buffer R7 winner) ----------------
#define GBM 128
#define GBN 64
#define GBK 32
#define ASTR 136
#define BSTR 72

__global__ __launch_bounds__(256) void gemm5_tc(
    const float* __restrict__ hs, const float* __restrict__ ce,
    const float* __restrict__ Wq,  const float* __restrict__ bq,
    const float* __restrict__ Wk,  const float* __restrict__ bk,
    const float* __restrict__ Wv,  const float* __restrict__ bv,
    const float* __restrict__ Wcq, const float* __restrict__ bcq,
    const float* __restrict__ Wck, const float* __restrict__ bck)
{
    const int which = blockIdx.z;
    const float* A;
    const float* Wt;
    const float* bias;
    float scale = 1.0f;
    float* C;
    switch (which) {
        case 0: A = hs; Wt = Wq;  bias = bq;  C = g_q;  break;
        case 1: A = hs; Wt = Wk;  bias = bk;  C = g_k;  break;
        case 2: A = hs; Wt = Wv;  bias = bv;  C = g_v;  break;
        case 3: A = ce; Wt = Wcq; bias = bcq; C = g_cq; scale = SCALE; break;
        default:A = ce; Wt = Wck; bias = bck; C = g_ck; break;
    }

    __shared__ uint32_t sA[GBK][ASTR];
    __shared__ uint32_t sB[GBK][BSTR];

    const int tid  = threadIdx.x;
    const int warp = tid >> 5;
    const int lane = tid & 31;
    const int wm   = warp & 3;
    const int wn   = warp >> 2;
    const int g    = lane >> 2;
    const int t4   = lane & 3;
    const int m0   = blockIdx.y * GBM;
    const int n0   = blockIdx.x * GBN;

    const int am = tid & 127;
    const int ak = (tid >> 7) * 16;
    const int bk2 = tid >> 3;
    const int bn2 = (tid & 7) * 8;

    const float* Abase = A  + (size_t)(m0 + am) * E + ak;
    const float* Bbase = Wt + (size_t)bk2 * E + n0 + bn2;

    float acc[2][4][4];
    #pragma unroll
    for (int mt = 0; mt < 2; mt++)
        #pragma unroll
        for (int nt = 0; nt < 4; nt++)
            #pragma unroll
            for (int x = 0; x < 4; x++) acc[mt][nt][x] = 0.f;

    for (int k0 = 0; k0 < E; k0 += GBK) {
        #pragma unroll
        for (int i = 0; i < 4; i++) {
            float4 v = *(const float4*)(Abase + k0 + i * 4);
            sA[ak + i*4 + 0][am] = f2tf32(v.x);
            sA[ak + i*4 + 1][am] = f2tf32(v.y);
            sA[ak + i*4 + 2][am] = f2tf32(v.z);
            sA[ak + i*4 + 3][am] = f2tf32(v.w);
        }
        #pragma unroll
        for (int i = 0; i < 2; i++) {
            float4 v = *(const float4*)(Bbase + (size_t)k0 * E + i * 4);
            uint4 u;
            u.x = f2tf32(v.x); u.y = f2tf32(v.y);
            u.z = f2tf32(v.z); u.w = f2tf32(v.w);
            *(uint4*)&sB[bk2][bn2 + i * 4] = u;
        }
        __syncthreads();

        #pragma unroll
        for (int ks = 0; ks < 4; ks++) {
            const int kk = ks * 8;
            uint32_t af[2][4];
            #pragma unroll
            for (int mt = 0; mt < 2; mt++) {
                int mb = wm * 32 + mt * 16 + g;
                af[mt][0] = sA[kk + t4    ][mb];
                af[mt][1] = sA[kk + t4    ][mb + 8];
                af[mt][2] = sA[kk + t4 + 4][mb];
                af[mt][3] = sA[kk + t4 + 4][mb + 8];
            }
            uint32_t bf[4][2];
            #pragma unroll
            for (int nt = 0; nt < 4; nt++) {
                int nb = wn * 32 + nt * 8 + g;
                bf[nt][0] = sB[kk + t4    ][nb];
                bf[nt][1] = sB[kk + t4 + 4][nb];
            }
            #pragma unroll
            for (int mt = 0; mt < 2; mt++)
                #pragma unroll
                for (int nt = 0; nt < 4; nt++)
                    MMA_TF32(acc[mt][nt],
                             af[mt][0], af[mt][1], af[mt][2], af[mt][3],
                             bf[nt][0], bf[nt][1]);
        }
        __syncthreads();
    }

    #pragma unroll
    for (int nt = 0; nt < 4; nt++) {
        int col = n0 + wn * 32 + nt * 8 + 2 * t4;
        float b0v = bias[col], b1v = bias[col + 1];
        #pragma unroll
        for (int mt = 0; mt < 2; mt++) {
            int row = m0 + wm * 32 + mt * 16 + g;
            float2 o;
            o.x = (acc[mt][nt][0] + b0v) * scale;
            o.y = (acc[mt][nt][1] + b1v) * scale;
            *(float2*)&C[(size_t)row * E + col] = o;
            o.x = (acc[mt][nt][2] + b0v) * scale;
            o.y = (acc[mt][nt][3] + b1v) * scale;
            *(float2*)&C[(size_t)(row + 8) * E + col] = o;
        }
    }
}

// ---------------- lam ----------------
__global__ __launch_bounds__(256) void lam_kernel(
    const float* __restrict__ Wlqc, const float* __restrict__ blqc,
    const float* __restrict__ Wlqq, const float* __restrict__ blqq,
    const float* __restrict__ Wlkc, const float* __restrict__ blkc,
    const float* __restrict__ Wlkk, const float* __restrict__ blkk)
{
    int gw   = (blockIdx.x * blockDim.x + threadIdx.x) >> 5;
    int lane = threadIdx.x & 31;
    if (gw >= S * Hh) return;
    int s = gw / Hh, h = gw % Hh;
    size_t base = (size_t)s * E + h * D;

    float a = g_cq[base + lane] * Wlqc[lane] + g_cq[base + lane + 32] * Wlqc[lane + 32]
            + g_q [base + lane] * Wlqq[lane] + g_q [base + lane + 32] * Wlqq[lane + 32];
    float b = g_ck[base + lane] * Wlkc[lane] + g_ck[base + lane + 32] * Wlkc[lane + 32]
            + g_k [base + lane] * Wlkk[lane] + g_k [base + lane + 32] * Wlkk[lane + 32];
    #pragma unroll
    for (int o = 16; o; o >>= 1) {
        a += __shfl_xor_sync(0xffffffffu, a, o);
        b += __shfl_xor_sync(0xffffffffu, b, o);
    }
    if (lane == 0) {
        float lq = 1.f / (1.f + __expf(-(a + blqc[0] + blqq[0])));
        float lk = 1.f / (1.f + __expf(-(b + blkc[0] + blkk[0])));
        g_lam[gw] = 1.f - lq - lk;
    }
}

// ---------------- quasi kernel (SIMT, R7 winner): npout[t] = lam * sigmoid(cq.cq + mask) ----------------
#define KSTR 64

__global__ __launch_bounds__(256) void quasi_kernel(
    const int* __restrict__ amask, float* __restrict__ npout)
{
    __shared__ float sCQT[64 * TQ];    // cq^T for query rows
    __shared__ float sCKT[64 * KSTR];  // cq key-block^T
    __shared__ float sFm[64];

    const int h   = blockIdx.y;
    const int q0  = blockIdx.x * TQ;
    const int tid = threadIdx.x;
    const int rg  = tid >> 4;          // 0..15
    const int cg  = tid & 15;
    const int r0  = rg << 1;           // rows r0, r0+1
    const int c0  = cg << 2;           // cols c0..c0+3

    {
        int lr = tid >> 3;             // 0..31
        int d0 = (tid & 7) << 3;       // 8 floats each
        const float4* cqp = (const float4*)(g_cq + (size_t)(q0 + lr) * E + h * D + d0);
        float4 c1 = cqp[0], c2 = cqp[1];
        sCQT[(d0+0)*TQ + lr] = c1.x; sCQT[(d0+1)*TQ + lr] = c1.y;
        sCQT[(d0+2)*TQ + lr] = c1.z; sCQT[(d0+3)*TQ + lr] = c1.w;
        sCQT[(d0+4)*TQ + lr] = c2.x; sCQT[(d0+5)*TQ + lr] = c2.y;
        sCQT[(d0+6)*TQ + lr] = c2.z; sCQT[(d0+7)*TQ + lr] = c2.w;
    }

    const float lam0 = g_lam[(q0 + r0 + 0) * Hh + h];
    const float lam1 = g_lam[(q0 + r0 + 1) * Hh + h];
    float* nprow0 = npout + ((size_t)(q0 + r0 + 0) * Hh + h) * TT;
    float* nprow1 = npout + ((size_t)(q0 + r0 + 1) * Hh + h) * TT;

    const int lc  = tid >> 2;          // 0..63
    const int ld0 = (tid & 3) << 4;    // 0,16,32,48

    for (int b = 0; b < NKB; b++) {
        const int kb0 = q0 - Wb + b * 64;
        __syncthreads();
        {
            int j = kb0 + lc;
            bool ok = (j >= 0) && (j < S);
            const float4* cp = (const float4*)(g_cq + (size_t)(ok ? j : 0) * E + h * D + ld0);
            #pragma unroll
            for (int u4 = 0; u4 < 4; u4++) {
                float4 cv = ok ? cp[u4] : make_float4(0.f,0.f,0.f,0.f);
                int dd = ld0 + u4 * 4;
                sCKT[(dd+0)*KSTR + lc] = cv.x; sCKT[(dd+1)*KSTR + lc] = cv.y;
                sCKT[(dd+2)*KSTR + lc] = cv.z; sCKT[(dd+3)*KSTR + lc] = cv.w;
            }
            if (tid < 64) {
                int jj = kb0 + tid;
                sFm[tid] = (jj >= 0 && jj < S && amask[jj] != 0) ? -10000.f : 0.f;
            }
        }
        __syncthreads();

        float acq[2][4] = {{0.f,0.f,0.f,0.f},{0.f,0.f,0.f,0.f}};
        #pragma unroll 8
        for (int kk = 0; kk < 64; kk++) {
            float2 cqv = *(const float2*)&sCQT[kk*TQ  + r0];
            float4 ckv = *(const float4*)&sCKT[kk*KSTR + c0];
            acq[0][0] += cqv.x*ckv.x; acq[0][1] += cqv.x*ckv.y;
            acq[0][2] += cqv.x*ckv.z; acq[0][3] += cqv.x*ckv.w;
            acq[1][0] += cqv.y*ckv.x; acq[1][1] += cqv.y*ckv.y;
            acq[1][2] += cqv.y*ckv.z; acq[1][3] += cqv.y*ckv.w;
        }

        #pragma unroll
        for (int jx = 0; jx < 4; jx++) {
            int c = c0 + jx;
            int j = kb0 + c;
            bool okj = (j >= 0) && (j < S);
            float fm = sFm[c];
            {
                int t = b * 64 + c - (r0 + 0);
                if (t >= 0 && t <= 512) {
                    float v = okj ? lam0 / (1.f + __expf(-(acq[0][jx] + fm))) : 0.f;
                    nprow0[t] = v;
                }
            }
            {
                int t = b * 64 + c - (r0 + 1);
                if (t >= 0 && t <= 512) {
                    float v = okj ? lam1 / (1.f + __expf(-(acq[1][jx] + fm))) : 0.f;
                    nprow1[t] = v;
                }
            }
        }
    }
}

// ---------------- attn kernel (SIMT, R7 winner): softmax band + combine with staged quasi ----------------
__global__ __launch_bounds__(256, 2) void attn_kernel(
    const int* __restrict__ amask, float* __restrict__ npout)
{
    __shared__ float sQT[64 * TQ];     // q^T (pre-scaled)
    __shared__ float sKT[64 * KSTR];   // k^T
    __shared__ float sFm[64];

    const int h   = blockIdx.y;
    const int q0  = blockIdx.x * TQ;
    const int tid = threadIdx.x;
    const int rg  = tid >> 4;
    const int cg  = tid & 15;
    const int r0  = rg << 1;
    const int c0  = cg << 2;

    {
        int lr = tid >> 3;
        int d0 = (tid & 7) << 3;
        const float4* qp = (const float4*)(g_q + (size_t)(q0 + lr) * E + h * D + d0);
        float4 q1 = qp[0], q2 = qp[1];
        sQT[(d0+0)*TQ + lr] = q1.x * SCALE; sQT[(d0+1)*TQ + lr] = q1.y * SCALE;
        sQT[(d0+2)*TQ + lr] = q1.z * SCALE; sQT[(d0+3)*TQ + lr] = q1.w * SCALE;
        sQT[(d0+4)*TQ + lr] = q2.x * SCALE; sQT[(d0+5)*TQ + lr] = q2.y * SCALE;
        sQT[(d0+6)*TQ + lr] = q2.z * SCALE; sQT[(d0+7)*TQ + lr] = q2.w * SCALE;
    }

    float aA[2][NKB*4];   // attn band (scores, then exp)

    const int lc  = tid >> 2;
    const int ld0 = (tid & 3) << 4;

    #pragma unroll
    for (int b = 0; b < NKB; b++) {
        const int kb0 = q0 - Wb + b * 64;
        __syncthreads();
        {
            int j = kb0 + lc;
            bool ok = (j >= 0) && (j < S);
            const float4* kp = (const float4*)(g_k + (size_t)(ok ? j : 0) * E + h * D + ld0);
            #pragma unroll
            for (int u4 = 0; u4 < 4; u4++) {
                float4 kv = ok ? kp[u4] : make_float4(0.f,0.f,0.f,0.f);
                int dd = ld0 + u4 * 4;
                sKT[(dd+0)*KSTR + lc] = kv.x; sKT[(dd+1)*KSTR + lc] = kv.y;
                sKT[(dd+2)*KSTR + lc] = kv.z; sKT[(dd+3)*KSTR + lc] = kv.w;
            }
            if (tid < 64) {
                int jj = kb0 + tid;
                sFm[tid] = (jj >= 0 && jj < S && amask[jj] != 0) ? -10000.f : 0.f;
            }
        }
        __syncthreads();

        float acc[2][4] = {{0.f,0.f,0.f,0.f},{0.f,0.f,0.f,0.f}};
        #pragma unroll 8
        for (int kk = 0; kk < 64; kk++) {
            float2 qv = *(const float2*)&sQT[kk*TQ  + r0];
            float4 kv = *(const float4*)&sKT[kk*KSTR + c0];
            acc[0][0] += qv.x*kv.x; acc[0][1] += qv.x*kv.y;
            acc[0][2] += qv.x*kv.z; acc[0][3] += qv.x*kv.w;
            acc[1][0] += qv.y*kv.x; acc[1][1] += qv.y*kv.y;
            acc[1][2] += qv.y*kv.z; acc[1][3] += qv.y*kv.w;
        }

        #pragma unroll
        for (int i = 0; i < 2; i++) {
            int r = r0 + i;
            #pragma unroll
            for (int jx = 0; jx < 4; jx++) {
                int c = c0 + jx;
                int t = b * 64 + c - r;
                int j = kb0 + c;
                bool valid = (t >= 0) && (t <= 512) && (j >= 0) && (j < S);
                aA[i][b*4+jx] = valid ? (acc[i][jx] + sFm[c]) : NEGV;
            }
        }
    }

    #pragma unroll
    for (int i = 0; i < 2; i++) {
        int r  = r0 + i;
        int ig = q0 + r;
        float m = NEGV;
        #pragma unroll
        for (int x = 0; x < NKB*4; x++) m = fmaxf(m, aA[i][x]);
        #pragma unroll
        for (int o = 8; o; o >>= 1) m = fmaxf(m, __shfl_xor_sync(0xffffffffu, m, o));
        float ssum = 0.f;
        #pragma unroll
        for (int x = 0; x < NKB*4; x++) {
            float e = __expf(aA[i][x] - m);
            aA[i][x] = e;
            ssum += e;
        }
        #pragma unroll
        for (int o = 8; o; o >>= 1) ssum += __shfl_xor_sync(0xffffffffu, ssum, o);
        float inv = 1.f / ssum;
        bool  qm  = (amask[ig] != 0);
        float* nprow = npout + ((size_t)ig * Hh + h) * TT;
        #pragma unroll
        for (int b = 0; b < NKB; b++) {
            #pragma unroll
            for (int jx = 0; jx < 4; jx++) {
                int t = b * 64 + c0 + jx - r;
                if (t >= 0 && t <= 512) {
                    float np = aA[i][b*4+jx] * inv + nprow[t];
                    nprow[t] = qm ? 0.f : np;
                }
            }
        }
    }
}

// ---------------- PV with tf32 MMA: out = band_pv(new_probs, v) ----------------
// Per CTA: 64 q-rows; per 64-key block a dense 64x64x64 GEMM on smem tiles.
// sP[r][c] tf32 (A, row-major m=r,k=c): frag banks (4g+t4)%32 conflict-free.
// sV[c][d] tf32 (B, col-major k=c,n=d): frag banks (4t4+g)%32 conflict-free.
#define PSTR 68
#define VSTR 68

__global__ __launch_bounds__(256) void pv_tc(
    float* __restrict__ outp, const float* __restrict__ npout)
{
    __shared__ uint32_t sP[TQP * PSTR];   // [64][68] tf32
    __shared__ uint32_t sV[64 * VSTR];    // [64][68] tf32

    const int h   = blockIdx.y;
    const int q0  = blockIdx.x * TQP;
    const int tid = threadIdx.x;
    const int warp = tid >> 5, lane = tid & 31;
    const int mw = warp >> 1;          // 0..3 -> rows 16mw..16mw+15
    const int nw = warp & 1;           // 0..1 -> cols 32nw..32nw+31
    const int g = lane >> 2, t4 = lane & 3;

    float acc[4][4];
    #pragma unroll
    for (int nt = 0; nt < 4; nt++)
        #pragma unroll
        for (int x = 0; x < 4; x++) acc[nt][x] = 0.f;

    for (int b = 0; b < NKB; b++) {
        int kb0 = q0 - Wb + b * 64;
        __syncthreads();
        // load p tile (band gather, tf32)
        {
            int lr  = tid >> 2;            // 0..63
            int c0l = (tid & 3) << 4;      // 0,16,32,48
            const float* nprow = npout + ((size_t)(q0 + lr) * Hh + h) * TT;
            #pragma unroll
            for (int x4 = 0; x4 < 4; x4++) {
                int t0 = b * 64 + c0l + x4 * 4 - lr;
                uint4 u;
                u.x = (t0+0 >= 0 && t0+0 <= 512) ? f2tf32(nprow[t0+0]) : 0u;
                u.y = (t0+1 >= 0 && t0+1 <= 512) ? f2tf32(nprow[t0+1]) : 0u;
                u.z = (t0+2 >= 0 && t0+2 <= 512) ? f2tf32(nprow[t0+2]) : 0u;
                u.w = (t0+3 >= 0 && t0+3 <= 512) ? f2tf32(nprow[t0+3]) : 0u;
                *(uint4*)&sP[lr * PSTR + c0l + x4 * 4] = u;
            }
        }
        // load v tile [c][d] (tf32)
        {
            int c   = tid >> 2;            // 0..63
            int d0l = (tid & 3) << 4;      // 0,16,32,48
            int j = kb0 + c;
            bool ok = (j >= 0) && (j < S);
            const float4* vp = (const float4*)(g_v + (size_t)(ok ? j : 0) * E + h * D + d0l);
            #pragma unroll
            for (int u4 = 0; u4 < 4; u4++) {
                float4 x = ok ? vp[u4] : make_float4(0.f,0.f,0.f,0.f);
                uint4 u;
                u.x = f2tf32(x.x); u.y = f2tf32(x.y);
                u.z = f2tf32(x.z); u.w = f2tf32(x.w);
                *(uint4*)&sV[c * VSTR + d0l + u4 * 4] = u;
            }
        }
        __syncthreads();

        const int m0l = mw * 16;
        #pragma unroll
        for (int ks = 0; ks < 8; ks++) {
            const int kk = ks * 8;
            uint32_t a0 = sP[(m0l + g    ) * PSTR + kk + t4];
            uint32_t a1 = sP[(m0l + g + 8) * PSTR + kk + t4];
            uint32_t a2 = sP[(m0l + g    ) * PSTR + kk + t4 + 4];
            uint32_t a3 = sP[(m0l + g + 8) * PSTR + kk + t4 + 4];
            #pragma unroll
            for (int nt = 0; nt < 4; nt++) {
                int nb = nw * 32 + nt * 8 + g;
                uint32_t b0 = sV[(kk + t4    ) * VSTR + nb];
                uint32_t b1 = sV[(kk + t4 + 4) * VSTR + nb];
                MMA_TF32(acc[nt], a0, a1, a2, a3, b0, b1);
            }
        }
    }

    // epilogue
    #pragma unroll
    for (int nt = 0; nt < 4; nt++) {
        int col = nw * 32 + nt * 8 + 2 * t4;
        int row = q0 + mw * 16 + g;
        float2 o;
        o.x = acc[nt][0]; o.y = acc[nt][1];
        *(float2*)(outp + (size_t)row * E + h * D + col) = o;
        o.x = acc[nt][2]; o.y = acc[nt][3];
        *(float2*)(outp + (size_t)(row + 8) * E + h * D + col) = o;
    }
}

// ---------------- launch ----------------
extern "C" void kernel_launch(void* const* d_in, const int* in_sizes, int n_in,
                              void* d_out, int out_size)
{
    (void)in_sizes; (void)n_in; (void)out_size;

    const float* hs    = (const float*)d_in[0];
    const float* ce    = (const float*)d_in[1];
    const int*   amask = (const int*)  d_in[2];
    // d_in[3] is is_index_masked == (attention_mask != 0); derived from amask.
    const float* Wq   = (const float*)d_in[4];
    const float* bq   = (const float*)d_in[5];
    const float* Wk   = (const float*)d_in[6];
    const float* bk   = (const float*)d_in[7];
    const float* Wv   = (const float*)d_in[8];
    const float* bv   = (const float*)d_in[9];
    const float* Wcq  = (const float*)d_in[10];
    const float* bcq  = (const float*)d_in[11];
    const float* Wck  = (const float*)d_in[12];
    const float* bck  = (const float*)d_in[13];
    const float* Wlqc = (const float*)d_in[14];
    const float* blqc = (const float*)d_in[15];
    const float* Wlqq = (const float*)d_in[16];
    const float* blqq = (const float*)d_in[17];
    const float* Wlkc = (const float*)d_in[18];
    const float* blkc = (const float*)d_in[19];
    const float* Wlkk = (const float*)d_in[20];
    const float* blkk = (const float*)d_in[21];

    float* outp  = (float*)d_out;
    float* npout = outp + (size_t)S * E;   // tuple output: [out | new_probs]

    dim3 gg(E / GBN, S / GBM, 5);
    gemm5_tc<<<gg, 256>>>(hs, ce, Wq, bq, Wk, bk, Wv, bv, Wcq, bcq, Wck, bck);

    lam_kernel<<<(S * Hh) / 8, 256>>>(Wlqc, blqc, Wlqq, blqq, Wlkc, blkc, Wlkk, blkk);

    quasi_kernel<<<dim3(S / TQ, Hh), 256>>>(amask, npout);

    attn_kernel<<<dim3(S / TQ, Hh), 256>>>(amask, npout);

    pv_tc<<<dim3(S / TQP, Hh), 256>>>(outp, npout);
}

// round 13
// speedup vs baseline: 1.3589x; 1.1445x over previous
#include <cuda_runtime.h>
#include <math.h>
#include <stdint.h>

#define S 4096
#define E 768
#define Hh 12
#define D 64
#define Wb 256
#define TT 513          // band width 2W+1
#define TQ 32           // qk: query rows per CTA
#define TQP 64          // pv: query rows per CTA
#define NKB 9           // 64-wide key blocks
#define NEGV -1000000000.0f
#define SCALE 0.125f    // 1/sqrt(64)

// ---------------- scratch (static __device__, no allocations) ----------------
__device__ float g_q [S*E];
__device__ float g_k [S*E];
__device__ float g_v [S*E];
__device__ float g_cq[S*E];
__device__ float g_ck[S*E];
__device__ float g_lam[S*Hh];

__device__ __forceinline__ uint32_t f2tf32(float f) {
    uint32_t u;
    asm("cvt.rna.tf32.f32 %0, %1;" : "=r"(u) : "f"(f));
    return u;
}

#define MMA_TF32(acc, a0,a1,a2,a3, b0,b1)                                    \
    asm("mma.sync.aligned.m16n8k8.row.col.f32.tf32.tf32.f32 "                \
        "{%0,%1,%2,%3}, {%4,%5,%6,%7}, {%8,%9}, {%0,%1,%2,%3};"              \
        : "+f"(acc[0]), "+f"(acc[1]), "+f"(acc[2]), "+f"(acc[3])             \
        : "r"(a0), "r"(a1), "r"(a2), "r"(a3), "r"(b0), "r"(b1))

// ---------------- projection GEMM (tf32 mma.sync, 128x128 CTA tile) ----------------
// 256 threads = 8 warps: wm=warp&3 (m 32-tile), wn=warp>>2 (n 64-tile).
// Warp tile 32x64: per ks 8 A-frag + 16 B-frag LDS -> 16 MMAs.
#define GBM 128
#define GBN 128
#define GBK 32
#define ASTR 136
#define BSTR 136

__global__ __launch_bounds__(256) void gemm5_tc(
    const float* __restrict__ hs, const float* __restrict__ ce,
    const float* __restrict__ Wq,  const float* __restrict__ bq,
    const float* __restrict__ Wk,  const float* __restrict__ bk,
    const float* __restrict__ Wv,  const float* __restrict__ bv,
    const float* __restrict__ Wcq, const float* __restrict__ bcq,
    const float* __restrict__ Wck, const float* __restrict__ bck)
{
    const int which = blockIdx.z;
    const float* A;
    const float* Wt;
    const float* bias;
    float scale = 1.0f;
    float* C;
    switch (which) {
        case 0: A = hs; Wt = Wq;  bias = bq;  C = g_q;  break;
        case 1: A = hs; Wt = Wk;  bias = bk;  C = g_k;  break;
        case 2: A = hs; Wt = Wv;  bias = bv;  C = g_v;  break;
        case 3: A = ce; Wt = Wcq; bias = bcq; C = g_cq; scale = SCALE; break;
        default:A = ce; Wt = Wck; bias = bck; C = g_ck; break;
    }

    __shared__ uint32_t sA[GBK][ASTR];
    __shared__ uint32_t sB[GBK][BSTR];

    const int tid  = threadIdx.x;
    const int warp = tid >> 5;
    const int lane = tid & 31;
    const int wm   = warp & 3;           // m offset wm*32
    const int wn   = warp >> 2;          // n offset wn*64
    const int g    = lane >> 2;
    const int t4   = lane & 3;
    const int m0   = blockIdx.y * GBM;
    const int n0   = blockIdx.x * GBN;

    // A loader: row am (0..127), k base ak (0 or 16), 16 floats along k
    const int am = tid & 127;
    const int ak = (tid >> 7) * 16;
    // B loader: k row bk2 (0..31), n base bn2 = (tid&7)*4; 4 float4 at +32-col strides
    const int bk2 = tid >> 3;
    const int bn2 = (tid & 7) * 4;

    const float* Abase = A  + (size_t)(m0 + am) * E + ak;
    const float* Bbase = Wt + (size_t)bk2 * E + n0 + bn2;

    float acc[2][8][4];
    #pragma unroll
    for (int mt = 0; mt < 2; mt++)
        #pragma unroll
        for (int nt = 0; nt < 8; nt++)
            #pragma unroll
            for (int x = 0; x < 4; x++) acc[mt][nt][x] = 0.f;

    for (int k0 = 0; k0 < E; k0 += GBK) {
        #pragma unroll
        for (int i = 0; i < 4; i++) {
            float4 v = *(const float4*)(Abase + k0 + i * 4);
            sA[ak + i*4 + 0][am] = f2tf32(v.x);
            sA[ak + i*4 + 1][am] = f2tf32(v.y);
            sA[ak + i*4 + 2][am] = f2tf32(v.z);
            sA[ak + i*4 + 3][am] = f2tf32(v.w);
        }
        #pragma unroll
        for (int j = 0; j < 4; j++) {
            float4 v = *(const float4*)(Bbase + (size_t)k0 * E + j * 32);
            uint4 u;
            u.x = f2tf32(v.x); u.y = f2tf32(v.y);
            u.z = f2tf32(v.z); u.w = f2tf32(v.w);
            *(uint4*)&sB[bk2][bn2 + j * 32] = u;
        }
        __syncthreads();

        #pragma unroll
        for (int ks = 0; ks < 4; ks++) {
            const int kk = ks * 8;
            uint32_t af[2][4];
            #pragma unroll
            for (int mt = 0; mt < 2; mt++) {
                int mb = wm * 32 + mt * 16 + g;
                af[mt][0] = sA[kk + t4    ][mb];
                af[mt][1] = sA[kk + t4    ][mb + 8];
                af[mt][2] = sA[kk + t4 + 4][mb];
                af[mt][3] = sA[kk + t4 + 4][mb + 8];
            }
            uint32_t bf[8][2];
            #pragma unroll
            for (int nt = 0; nt < 8; nt++) {
                int nb = wn * 64 + nt * 8 + g;
                bf[nt][0] = sB[kk + t4    ][nb];
                bf[nt][1] = sB[kk + t4 + 4][nb];
            }
            #pragma unroll
            for (int mt = 0; mt < 2; mt++)
                #pragma unroll
                for (int nt = 0; nt < 8; nt++)
                    MMA_TF32(acc[mt][nt],
                             af[mt][0], af[mt][1], af[mt][2], af[mt][3],
                             bf[nt][0], bf[nt][1]);
        }
        __syncthreads();
    }

    #pragma unroll
    for (int nt = 0; nt < 8; nt++) {
        int col = n0 + wn * 64 + nt * 8 + 2 * t4;
        float b0v = bias[col], b1v = bias[col + 1];
        #pragma unroll
        for (int mt = 0; mt < 2; mt++) {
            int row = m0 + wm * 32 + mt * 16 + g;
            float2 o;
            o.x = (acc[mt][nt][0] + b0v) * scale;
            o.y = (acc[mt][nt][1] + b1v) * scale;
            *(float2*)&C[(size_t)row * E + col] = o;
            o.x = (acc[mt][nt][2] + b0v) * scale;
            o.y = (acc[mt][nt][3] + b1v) * scale;
            *(float2*)&C[(size_t)(row + 8) * E + col] = o;
        }
    }
}

// ---------------- lam ----------------
__global__ __launch_bounds__(256) void lam_kernel(
    const float* __restrict__ Wlqc, const float* __restrict__ blqc,
    const float* __restrict__ Wlqq, const float* __restrict__ blqq,
    const float* __restrict__ Wlkc, const float* __restrict__ blkc,
    const float* __restrict__ Wlkk, const float* __restrict__ blkk)
{
    int gw   = (blockIdx.x * blockDim.x + threadIdx.x) >> 5;
    int lane = threadIdx.x & 31;
    if (gw >= S * Hh) return;
    int s = gw / Hh, h = gw % Hh;
    size_t base = (size_t)s * E + h * D;

    float a = g_cq[base + lane] * Wlqc[lane] + g_cq[base + lane + 32] * Wlqc[lane + 32]
            + g_q [base + lane] * Wlqq[lane] + g_q [base + lane + 32] * Wlqq[lane + 32];
    float b = g_ck[base + lane] * Wlkc[lane] + g_ck[base + lane + 32] * Wlkc[lane + 32]
            + g_k [base + lane] * Wlkk[lane] + g_k [base + lane + 32] * Wlkk[lane + 32];
    #pragma unroll
    for (int o = 16; o; o >>= 1) {
        a += __shfl_xor_sync(0xffffffffu, a, o);
        b += __shfl_xor_sync(0xffffffffu, b, o);
    }
    if (lane == 0) {
        float lq = 1.f / (1.f + __expf(-(a + blqc[0] + blqq[0])));
        float lk = 1.f / (1.f + __expf(-(b + blkc[0] + blkk[0])));
        g_lam[gw] = 1.f - lq - lk;
    }
}

// ---------------- quasi kernel (SIMT, R7 winner): npout[t] = lam * sigmoid(cq.cq + mask) ----------------
#define KSTR 64

__global__ __launch_bounds__(256) void quasi_kernel(
    const int* __restrict__ amask, float* __restrict__ npout)
{
    __shared__ float sCQT[64 * TQ];    // cq^T for query rows
    __shared__ float sCKT[64 * KSTR];  // cq key-block^T
    __shared__ float sFm[64];

    const int h   = blockIdx.y;
    const int q0  = blockIdx.x * TQ;
    const int tid = threadIdx.x;
    const int rg  = tid >> 4;          // 0..15
    const int cg  = tid & 15;
    const int r0  = rg << 1;           // rows r0, r0+1
    const int c0  = cg << 2;           // cols c0..c0+3

    {
        int lr = tid >> 3;             // 0..31
        int d0 = (tid & 7) << 3;       // 8 floats each
        const float4* cqp = (const float4*)(g_cq + (size_t)(q0 + lr) * E + h * D + d0);
        float4 c1 = cqp[0], c2 = cqp[1];
        sCQT[(d0+0)*TQ + lr] = c1.x; sCQT[(d0+1)*TQ + lr] = c1.y;
        sCQT[(d0+2)*TQ + lr] = c1.z; sCQT[(d0+3)*TQ + lr] = c1.w;
        sCQT[(d0+4)*TQ + lr] = c2.x; sCQT[(d0+5)*TQ + lr] = c2.y;
        sCQT[(d0+6)*TQ + lr] = c2.z; sCQT[(d0+7)*TQ + lr] = c2.w;
    }

    const float lam0 = g_lam[(q0 + r0 + 0) * Hh + h];
    const float lam1 = g_lam[(q0 + r0 + 1) * Hh + h];
    float* nprow0 = npout + ((size_t)(q0 + r0 + 0) * Hh + h) * TT;
    float* nprow1 = npout + ((size_t)(q0 + r0 + 1) * Hh + h) * TT;

    const int lc  = tid >> 2;          // 0..63
    const int ld0 = (tid & 3) << 4;    // 0,16,32,48

    for (int b = 0; b < NKB; b++) {
        const int kb0 = q0 - Wb + b * 64;
        __syncthreads();
        {
            int j = kb0 + lc;
            bool ok = (j >= 0) && (j < S);
            const float4* cp = (const float4*)(g_cq + (size_t)(ok ? j : 0) * E + h * D + ld0);
            #pragma unroll
            for (int u4 = 0; u4 < 4; u4++) {
                float4 cv = ok ? cp[u4] : make_float4(0.f,0.f,0.f,0.f);
                int dd = ld0 + u4 * 4;
                sCKT[(dd+0)*KSTR + lc] = cv.x; sCKT[(dd+1)*KSTR + lc] = cv.y;
                sCKT[(dd+2)*KSTR + lc] = cv.z; sCKT[(dd+3)*KSTR + lc] = cv.w;
            }
            if (tid < 64) {
                int jj = kb0 + tid;
                sFm[tid] = (jj >= 0 && jj < S && amask[jj] != 0) ? -10000.f : 0.f;
            }
        }
        __syncthreads();

        float acq[2][4] = {{0.f,0.f,0.f,0.f},{0.f,0.f,0.f,0.f}};
        #pragma unroll 8
        for (int kk = 0; kk < 64; kk++) {
            float2 cqv = *(const float2*)&sCQT[kk*TQ  + r0];
            float4 ckv = *(const float4*)&sCKT[kk*KSTR + c0];
            acq[0][0] += cqv.x*ckv.x; acq[0][1] += cqv.x*ckv.y;
            acq[0][2] += cqv.x*ckv.z; acq[0][3] += cqv.x*ckv.w;
            acq[1][0] += cqv.y*ckv.x; acq[1][1] += cqv.y*ckv.y;
            acq[1][2] += cqv.y*ckv.z; acq[1][3] += cqv.y*ckv.w;
        }

        #pragma unroll
        for (int jx = 0; jx < 4; jx++) {
            int c = c0 + jx;
            int j = kb0 + c;
            bool okj = (j >= 0) && (j < S);
            float fm = sFm[c];
            {
                int t = b * 64 + c - (r0 + 0);
                if (t >= 0 && t <= 512) {
                    float v = okj ? lam0 / (1.f + __expf(-(acq[0][jx] + fm))) : 0.f;
                    nprow0[t] = v;
                }
            }
            {
                int t = b * 64 + c - (r0 + 1);
                if (t >= 0 && t <= 512) {
                    float v = okj ? lam1 / (1.f + __expf(-(acq[1][jx] + fm))) : 0.f;
                    nprow1[t] = v;
                }
            }
        }
    }
}

// ---------------- attn kernel (SIMT, R7 winner): softmax band + combine with staged quasi ----------------
__global__ __launch_bounds__(256, 2) void attn_kernel(
    const int* __restrict__ amask, float* __restrict__ npout)
{
    __shared__ float sQT[64 * TQ];     // q^T (pre-scaled)
    __shared__ float sKT[64 * KSTR];   // k^T
    __shared__ float sFm[64];

    const int h   = blockIdx.y;
    const int q0  = blockIdx.x * TQ;
    const int tid = threadIdx.x;
    const int rg  = tid >> 4;
    const int cg  = tid & 15;
    const int r0  = rg << 1;
    const int c0  = cg << 2;

    {
        int lr = tid >> 3;
        int d0 = (tid & 7) << 3;
        const float4* qp = (const float4*)(g_q + (size_t)(q0 + lr) * E + h * D + d0);
        float4 q1 = qp[0], q2 = qp[1];
        sQT[(d0+0)*TQ + lr] = q1.x * SCALE; sQT[(d0+1)*TQ + lr] = q1.y * SCALE;
        sQT[(d0+2)*TQ + lr] = q1.z * SCALE; sQT[(d0+3)*TQ + lr] = q1.w * SCALE;
        sQT[(d0+4)*TQ + lr] = q2.x * SCALE; sQT[(d0+5)*TQ + lr] = q2.y * SCALE;
        sQT[(d0+6)*TQ + lr] = q2.z * SCALE; sQT[(d0+7)*TQ + lr] = q2.w * SCALE;
    }

    float aA[2][NKB*4];   // attn band (scores, then exp)

    const int lc  = tid >> 2;
    const int ld0 = (tid & 3) << 4;

    #pragma unroll
    for (int b = 0; b < NKB; b++) {
        const int kb0 = q0 - Wb + b * 64;
        __syncthreads();
        {
            int j = kb0 + lc;
            bool ok = (j >= 0) && (j < S);
            const float4* kp = (const float4*)(g_k + (size_t)(ok ? j : 0) * E + h * D + ld0);
            #pragma unroll
            for (int u4 = 0; u4 < 4; u4++) {
                float4 kv = ok ? kp[u4] : make_float4(0.f,0.f,0.f,0.f);
                int dd = ld0 + u4 * 4;
                sKT[(dd+0)*KSTR + lc] = kv.x; sKT[(dd+1)*KSTR + lc] = kv.y;
                sKT[(dd+2)*KSTR + lc] = kv.z; sKT[(dd+3)*KSTR + lc] = kv.w;
            }
            if (tid < 64) {
                int jj = kb0 + tid;
                sFm[tid] = (jj >= 0 && jj < S && amask[jj] != 0) ? -10000.f : 0.f;
            }
        }
        __syncthreads();

        float acc[2][4] = {{0.f,0.f,0.f,0.f},{0.f,0.f,0.f,0.f}};
        #pragma unroll 8
        for (int kk = 0; kk < 64; kk++) {
            float2 qv = *(const float2*)&sQT[kk*TQ  + r0];
            float4 kv = *(const float4*)&sKT[kk*KSTR + c0];
            acc[0][0] += qv.x*kv.x; acc[0][1] += qv.x*kv.y;
            acc[0][2] += qv.x*kv.z; acc[0][3] += qv.x*kv.w;
            acc[1][0] += qv.y*kv.x; acc[1][1] += qv.y*kv.y;
            acc[1][2] += qv.y*kv.z; acc[1][3] += qv.y*kv.w;
        }

        #pragma unroll
        for (int i = 0; i < 2; i++) {
            int r = r0 + i;
            #pragma unroll
            for (int jx = 0; jx < 4; jx++) {
                int c = c0 + jx;
                int t = b * 64 + c - r;
                int j = kb0 + c;
                bool valid = (t >= 0) && (t <= 512) && (j >= 0) && (j < S);
                aA[i][b*4+jx] = valid ? (acc[i][jx] + sFm[c]) : NEGV;
            }
        }
    }

    #pragma unroll
    for (int i = 0; i < 2; i++) {
        int r  = r0 + i;
        int ig = q0 + r;
        float m = NEGV;
        #pragma unroll
        for (int x = 0; x < NKB*4; x++) m = fmaxf(m, aA[i][x]);
        #pragma unroll
        for (int o = 8; o; o >>= 1) m = fmaxf(m, __shfl_xor_sync(0xffffffffu, m, o));
        float ssum = 0.f;
        #pragma unroll
        for (int x = 0; x < NKB*4; x++) {
            float e = __expf(aA[i][x] - m);
            aA[i][x] = e;
            ssum += e;
        }
        #pragma unroll
        for (int o = 8; o; o >>= 1) ssum += __shfl_xor_sync(0xffffffffu, ssum, o);
        float inv = 1.f / ssum;
        bool  qm  = (amask[ig] != 0);
        float* nprow = npout + ((size_t)ig * Hh + h) * TT;
        #pragma unroll
        for (int b = 0; b < NKB; b++) {
            #pragma unroll
            for (int jx = 0; jx < 4; jx++) {
                int t = b * 64 + c0 + jx - r;
                if (t >= 0 && t <= 512) {
                    float np = aA[i][b*4+jx] * inv + nprow[t];
                    nprow[t] = qm ? 0.f : np;
                }
            }
        }
    }
}

// ---------------- PV (SIMT, R7 winner): out = band_pv(new_probs, v) ----------------
#define PSTR 68
#define VSTR 68

__global__ __launch_bounds__(256) void pv_kernel(
    float* __restrict__ outp, const float* __restrict__ npout)
{
    __shared__ float sP[TQP * PSTR];   // [64][68]
    __shared__ float sV[64 * VSTR];    // [64][68]

    const int h   = blockIdx.y;
    const int q0  = blockIdx.x * TQP;
    const int tid = threadIdx.x;
    const int rg  = tid >> 4;          // rows 4rg..4rg+3
    const int dg  = tid & 15;          // d = 4dg..4dg+3

    float acc[4][4];
    #pragma unroll
    for (int i = 0; i < 4; i++)
        #pragma unroll
        for (int j = 0; j < 4; j++) acc[i][j] = 0.f;

    for (int b = 0; b < NKB; b++) {
        int kb0 = q0 - Wb + b * 64;
        __syncthreads();
        {
            int lr  = tid >> 2;
            int c0l = (tid & 3) << 4;
            const float* nprow = npout + ((size_t)(q0 + lr) * Hh + h) * TT;
            #pragma unroll
            for (int x4 = 0; x4 < 4; x4++) {
                int t0 = b * 64 + c0l + x4 * 4 - lr;
                float4 pv4;
                pv4.x = (t0+0 >= 0 && t0+0 <= 512) ? nprow[t0+0] : 0.f;
                pv4.y = (t0+1 >= 0 && t0+1 <= 512) ? nprow[t0+1] : 0.f;
                pv4.z = (t0+2 >= 0 && t0+2 <= 512) ? nprow[t0+2] : 0.f;
                pv4.w = (t0+3 >= 0 && t0+3 <= 512) ? nprow[t0+3] : 0.f;
                *(float4*)&sP[lr * PSTR + c0l + x4 * 4] = pv4;
            }
        }
        {
            int c   = tid >> 2;
            int d0l = (tid & 3) << 4;
            int j = kb0 + c;
            bool ok = (j >= 0) && (j < S);
            const float4* vp = (const float4*)(g_v + (size_t)(ok ? j : 0) * E + h * D + d0l);
            #pragma unroll
            for (int u4 = 0; u4 < 4; u4++) {
                float4 x = ok ? vp[u4] : make_float4(0.f,0.f,0.f,0.f);
                *(float4*)&sV[c * VSTR + d0l + u4 * 4] = x;
            }
        }
        __syncthreads();

        #pragma unroll 4
        for (int c = 0; c < 64; c++) {
            float4 vv = *(const float4*)&sV[c * VSTR + 4 * dg];
            float p0 = sP[(4*rg+0) * PSTR + c];
            float p1 = sP[(4*rg+1) * PSTR + c];
            float p2 = sP[(4*rg+2) * PSTR + c];
            float p3 = sP[(4*rg+3) * PSTR + c];
            acc[0][0] += p0*vv.x; acc[0][1] += p0*vv.y; acc[0][2] += p0*vv.z; acc[0][3] += p0*vv.w;
            acc[1][0] += p1*vv.x; acc[1][1] += p1*vv.y; acc[1][2] += p1*vv.z; acc[1][3] += p1*vv.w;
            acc[2][0] += p2*vv.x; acc[2][1] += p2*vv.y; acc[2][2] += p2*vv.z; acc[2][3] += p2*vv.w;
            acc[3][0] += p3*vv.x; acc[3][1] += p3*vv.y; acc[3][2] += p3*vv.z; acc[3][3] += p3*vv.w;
        }
    }

    #pragma unroll
    for (int i = 0; i < 4; i++) {
        float4 o;
        o.x = acc[i][0]; o.y = acc[i][1]; o.z = acc[i][2]; o.w = acc[i][3];
        *(float4*)(outp + (size_t)(q0 + 4*rg + i) * E + h * D + 4 * dg) = o;
    }
}

// ---------------- launch ----------------
extern "C" void kernel_launch(void* const* d_in, const int* in_sizes, int n_in,
                              void* d_out, int out_size)
{
    (void)in_sizes; (void)n_in; (void)out_size;

    const float* hs    = (const float*)d_in[0];
    const float* ce    = (const float*)d_in[1];
    const int*   amask = (const int*)  d_in[2];
    // d_in[3] is is_index_masked == (attention_mask != 0); derived from amask.
    const float* Wq   = (const float*)d_in[4];
    const float* bq   = (const float*)d_in[5];
    const float* Wk   = (const float*)d_in[6];
    const float* bk   = (const float*)d_in[7];
    const float* Wv   = (const float*)d_in[8];
    const float* bv   = (const float*)d_in[9];
    const float* Wcq  = (const float*)d_in[10];
    const float* bcq  = (const float*)d_in[11];
    const float* Wck  = (const float*)d_in[12];
    const float* bck  = (const float*)d_in[13];
    const float* Wlqc = (const float*)d_in[14];
    const float* blqc = (const float*)d_in[15];
    const float* Wlqq = (const float*)d_in[16];
    const float* blqq = (const float*)d_in[17];
    const float* Wlkc = (const float*)d_in[18];
    const float* blkc = (const float*)d_in[19];
    const float* Wlkk = (const float*)d_in[20];
    const float* blkk = (const float*)d_in[21];

    float* outp  = (float*)d_out;
    float* npout = outp + (size_t)S * E;   // tuple output: [out | new_probs]

    dim3 gg(E / GBN, S / GBM, 5);
    gemm5_tc<<<gg, 256>>>(hs, ce, Wq, bq, Wk, bk, Wv, bv, Wcq, bcq, Wck, bck);

    lam_kernel<<<(S * Hh) / 8, 256>>>(Wlqc, blqc, Wlqq, blqq, Wlkc, blkc, Wlkk, blkk);

    quasi_kernel<<<dim3(S / TQ, Hh), 256>>>(amask, npout);

    attn_kernel<<<dim3(S / TQ, Hh), 256>>>(amask, npout);

    pv_kernel<<<dim3(S / TQP, Hh), 256>>>(outp, npout);
}